// round 6
// baseline (speedup 1.0000x reference)
#include <cuda_runtime.h>
#include <cstdint>

#define IN_DIM   256
#define OUT_DIM  64
#define HCOLS    192   // [hp | lp | i]
#define MAX_NODES 100000
#define MAX_EDGES 3300000

// ---------------- scratch (device globals: no allocations allowed) ----------
__device__ float g_hall[(size_t)MAX_NODES * HCOLS];   // x @ [Whp|Wlp|Wi] + b
__device__ int   g_deg [MAX_NODES];
__device__ int   g_cur [MAX_NODES];                   // scatter cursors
__device__ int   g_rowp[MAX_NODES + 1];               // CSR row pointers (by dst)
__device__ int   g_adj [MAX_EDGES];                   // CSR column (src) indices
__device__ float g_isq [MAX_NODES];                   // 1/sqrt(deg)
__device__ float g_inv [MAX_NODES];                   // 1/deg
__device__ float g_Wall[IN_DIM * HCOLS];
__device__ float g_ball[HCOLS];
__device__ int   g_is64;                              // edge_index dtype flag

// ---------------- edge dtype detector (1 thread) -----------------------------
// If the buffer really is int64, every sampled value lies in [0, n). If it is
// int32, the int64 view packs two indices per word -> values >= 2^32 (or
// negative) with overwhelming probability across 64 samples.
__global__ void k_detect(const void* __restrict__ ei, int E, int n) {
    const long long* p = (const long long*)ei;
    int m = E < 64 ? E : 64;
    int ok = (E > 0) ? 1 : 0;
    for (int j = 0; j < m; j++) {
        long long v = p[j];   // first 64 words stay within even an int32-sized buffer
        if (v < 0 || v >= (long long)n) { ok = 0; break; }
    }
    g_is64 = ok;
}

__device__ __forceinline__ int edge_at(const void* ei, size_t idx) {
    if (g_is64) return (int)((const long long*)ei)[idx];
    return ((const int*)ei)[idx];
}

// ---------------- zero deg + cursors (deterministic per launch) --------------
__global__ void k_zero(int n) {
    int i = blockIdx.x * blockDim.x + threadIdx.x;
    if (i < n) { g_deg[i] = 0; g_cur[i] = 0; }
}

// ---------------- pack weights: W_all[256][192], b_all[192] ------------------
__global__ void k_prep_w(const float* __restrict__ Whp, const float* __restrict__ bhp,
                         const float* __restrict__ Wlp, const float* __restrict__ blp,
                         const float* __restrict__ Wi,  const float* __restrict__ bi) {
    int idx = blockIdx.x * blockDim.x + threadIdx.x;
    if (idx < IN_DIM * HCOLS) {
        int k = idx / HCOLS, j = idx % HCOLS;
        float v;
        if      (j < 64)  v = Whp[k * 64 + j];
        else if (j < 128) v = Wlp[k * 64 + (j - 64)];
        else              v = Wi [k * 64 + (j - 128)];
        g_Wall[idx] = v;
    }
    if (idx < HCOLS) {
        g_ball[idx] = (idx < 64) ? bhp[idx] : (idx < 128 ? blp[idx - 64] : bi[idx - 128]);
    }
}

// ---------------- degree count (int atomics, bounds-guarded) -----------------
__global__ void k_deg(const void* __restrict__ ei, int E, int n) {
    int e = blockIdx.x * blockDim.x + threadIdx.x;
    if (e < E) {
        int dst = edge_at(ei, (size_t)E + e);
        if ((unsigned)dst < (unsigned)n) atomicAdd(&g_deg[dst], 1);
    }
}
__global__ void k_degfin(int n) {
    int i = blockIdx.x * blockDim.x + threadIdx.x;
    if (i < n) {
        float d = (float)g_deg[i] + 1.0f;   // self-loop
        g_isq[i] = rsqrtf(d);
        g_inv[i] = 1.0f / d;
    }
}

// ---------------- exclusive scan of degrees -> row_ptr (single block) --------
__global__ void __launch_bounds__(1024) k_scan(int n) {
    __shared__ int sh[1024];
    int carry = 0;   // warp-uniform running total
    for (int base = 0; base < n; base += 1024) {
        int i = base + threadIdx.x;
        sh[threadIdx.x] = (i < n) ? g_deg[i] : 0;
        __syncthreads();
#pragma unroll
        for (int off = 1; off < 1024; off <<= 1) {
            int t = (threadIdx.x >= off) ? sh[threadIdx.x - off] : 0;
            __syncthreads();
            sh[threadIdx.x] += t;
            __syncthreads();
        }
        if (i < n) g_rowp[i + 1] = carry + sh[threadIdx.x];   // inclusive -> rowp[i+1]
        carry += sh[1023];
        __syncthreads();
    }
    if (threadIdx.x == 0) g_rowp[0] = 0;
}

// ---------------- scatter edges into CSR (int cursor atomics, guarded) -------
__global__ void k_scatter(const void* __restrict__ ei, int E, int n) {
    int e = blockIdx.x * blockDim.x + threadIdx.x;
    if (e < E) {
        int src = edge_at(ei, (size_t)e);
        int dst = edge_at(ei, (size_t)E + e);
        if ((unsigned)src < (unsigned)n && (unsigned)dst < (unsigned)n) {
            int pos = g_rowp[dst] + atomicAdd(&g_cur[dst], 1);
            if ((unsigned)pos < (unsigned)MAX_EDGES) g_adj[pos] = src;
        }
    }
}

// ---------------- GEMM: h_all = x @ W_all + b_all ---------------------------
// Tile: BM=128, BN=64, BK=16; 256 threads; 8x4 micro-tile / thread.
__global__ void __launch_bounds__(256) k_gemm(const float* __restrict__ x, int M) {
    __shared__ float As[16][132];   // padded rows break bank conflicts on column reads
    __shared__ float Bs[16][64];

    const int tid = threadIdx.x;
    const int m0 = blockIdx.x * 128;
    const int n0 = blockIdx.y * 64;

    const int arow = tid >> 2;
    const int ak4  = (tid & 3) * 4;
    const int brow = tid >> 4;
    const int bc4  = (tid & 15) * 4;
    const int rowBase = (tid >> 4) * 8;
    const int colBase = (tid & 15) * 4;

    float acc[8][4];
#pragma unroll
    for (int i = 0; i < 8; i++)
#pragma unroll
        for (int j = 0; j < 4; j++) acc[i][j] = 0.f;

    for (int k0 = 0; k0 < IN_DIM; k0 += 16) {
#pragma unroll
        for (int p = 0; p < 2; p++) {
            int m = m0 + arow + p * 64;
            int ms = m < M ? m : M - 1;                 // clamp (garbage rows never stored)
            float4 v = *reinterpret_cast<const float4*>(x + (size_t)ms * IN_DIM + k0 + ak4);
            As[ak4 + 0][arow + p * 64] = v.x;
            As[ak4 + 1][arow + p * 64] = v.y;
            As[ak4 + 2][arow + p * 64] = v.z;
            As[ak4 + 3][arow + p * 64] = v.w;
        }
        {
            float4 w = *reinterpret_cast<const float4*>(g_Wall + (size_t)(k0 + brow) * HCOLS + n0 + bc4);
            *reinterpret_cast<float4*>(&Bs[brow][bc4]) = w;
        }
        __syncthreads();

#pragma unroll
        for (int k = 0; k < 16; k++) {
            float4 a0 = *reinterpret_cast<const float4*>(&As[k][rowBase]);
            float4 a1 = *reinterpret_cast<const float4*>(&As[k][rowBase + 4]);
            float4 bb = *reinterpret_cast<const float4*>(&Bs[k][colBase]);
            float a[8] = {a0.x, a0.y, a0.z, a0.w, a1.x, a1.y, a1.z, a1.w};
            float b[4] = {bb.x, bb.y, bb.z, bb.w};
#pragma unroll
            for (int i = 0; i < 8; i++)
#pragma unroll
                for (int j = 0; j < 4; j++) acc[i][j] += a[i] * b[j];
        }
        __syncthreads();
    }

    float4 bias = *reinterpret_cast<const float4*>(g_ball + n0 + colBase);
#pragma unroll
    for (int i = 0; i < 8; i++) {
        int m = m0 + rowBase + i;
        if (m < M) {
            float4 o;
            o.x = acc[i][0] + bias.x;
            o.y = acc[i][1] + bias.y;
            o.z = acc[i][2] + bias.z;
            o.w = acc[i][3] + bias.w;
            *reinterpret_cast<float4*>(g_hall + (size_t)m * HCOLS + n0 + colBase) = o;
        }
    }
}

// ---------------- fused gather + epilogue (warp per node, NO float atomics) --
__global__ void __launch_bounds__(256) k_final(
    const float* __restrict__ wgh, const float* __restrict__ bgh,
    const float* __restrict__ wgl, const float* __restrict__ bgl,
    const float* __restrict__ wgi, const float* __restrict__ bgi,
    float* __restrict__ out, int n)
{
    __shared__ float sagg[8][128];
    int wslot = threadIdx.x >> 5;
    int node = blockIdx.x * 8 + wslot;
    int lane = threadIdx.x & 31;
    if (node >= n) return;

    int beg = g_rowp[node], end = g_rowp[node + 1];
    float isqd = g_isq[node];

    float4 acc = make_float4(0.f, 0.f, 0.f, 0.f);
    for (int p = beg; p < end; p++) {
        int src = g_adj[p];                            // warp-broadcast load
        float w = isqd * g_isq[src];
        float4 v = *reinterpret_cast<const float4*>(g_hall + (size_t)src * HCOLS + lane * 4);
        acc.x += w * v.x; acc.y += w * v.y; acc.z += w * v.z; acc.w += w * v.w;
    }
    *reinterpret_cast<float4*>(&sagg[wslot][lane * 4]) = acc;
    __syncwarp();

    const float* hrow = g_hall + (size_t)node * HCOLS;
    const float* arow = sagg[wslot];
    float inv = g_inv[node];

    float Hhp[2], Hlp[2], Hi[2];
    float gh = 0.f, gl = 0.f, gi = 0.f;
#pragma unroll
    for (int t = 0; t < 2; t++) {
        int d = lane + t * 32;
        float hp = hrow[d], lp = hrow[64 + d], hi = hrow[128 + d];
        float ah = arow[d], al = arow[64 + d];
        Hhp[t] = fmaxf(hp - (ah + inv * hp), 0.f);   // HP = relu(h - A_hat h)
        Hlp[t] = fmaxf(al + inv * lp, 0.f);          // LP = relu(A_hat h)
        Hi [t] = fmaxf(hi, 0.f);                     // I  = relu(h)
        gh += Hhp[t] * wgh[d];
        gl += Hlp[t] * wgl[d];
        gi += Hi [t] * wgi[d];
    }
#pragma unroll
    for (int o = 16; o > 0; o >>= 1) {
        gh += __shfl_xor_sync(0xFFFFFFFFu, gh, o);
        gl += __shfl_xor_sync(0xFFFFFFFFu, gl, o);
        gi += __shfl_xor_sync(0xFFFFFFFFu, gi, o);
    }
    gh += bgh[0]; gl += bgl[0]; gi += bgi[0];

    float o0 = gh * Hhp[0] + gl * Hlp[0] + gi * Hi[0];
    float o1 = gh * Hhp[1] + gl * Hlp[1] + gi * Hi[1];

    float m = fmaxf(o0, o1);
#pragma unroll
    for (int o = 16; o > 0; o >>= 1) m = fmaxf(m, __shfl_xor_sync(0xFFFFFFFFu, m, o));
    float s = expf(o0 - m) + expf(o1 - m);
#pragma unroll
    for (int o = 16; o > 0; o >>= 1) s += __shfl_xor_sync(0xFFFFFFFFu, s, o);
    float lse = m + logf(s);

    out[(size_t)node * 64 + lane]      = o0 - lse;
    out[(size_t)node * 64 + lane + 32] = o1 - lse;
}

// ---------------- host launch ------------------------------------------------
extern "C" void kernel_launch(void* const* d_in, const int* in_sizes, int n_in,
                              void* d_out, int out_size) {
    const float* x  = (const float*)d_in[0];
    const void*  ei = d_in[1];                      // int32 or int64; detected on-device
    const float* Whp = (const float*)d_in[2];
    const float* bhp = (const float*)d_in[3];
    const float* Wlp = (const float*)d_in[4];
    const float* blp = (const float*)d_in[5];
    const float* Wi  = (const float*)d_in[6];
    const float* bi  = (const float*)d_in[7];
    const float* wgh = (const float*)d_in[8];
    const float* bgh = (const float*)d_in[9];
    const float* wgl = (const float*)d_in[10];
    const float* bgl = (const float*)d_in[11];
    const float* wgi = (const float*)d_in[12];
    const float* bgi = (const float*)d_in[13];
    float* out = (float*)d_out;

    int n = in_sizes[0] / IN_DIM;   // 100000
    int E = in_sizes[1] / 2;        // 3200000

    k_detect<<<1, 1>>>(ei, E, n);
    k_zero<<<(n + 255) / 256, 256>>>(n);
    k_prep_w<<<(IN_DIM * HCOLS + 255) / 256, 256>>>(Whp, bhp, Wlp, blp, Wi, bi);
    k_deg<<<(E + 255) / 256, 256>>>(ei, E, n);
    k_degfin<<<(n + 255) / 256, 256>>>(n);
    k_scan<<<1, 1024>>>(n);
    k_scatter<<<(E + 255) / 256, 256>>>(ei, E, n);
    k_gemm<<<dim3((n + 127) / 128, 3), 256>>>(x, n);
    k_final<<<(n + 7) / 8, 256>>>(wgh, bgh, wgl, bgl, wgi, bgi, out, n);
}

// round 7
// speedup vs baseline: 1.6644x; 1.6644x over previous
#include <cuda_runtime.h>
#include <cstdint>

#define IN_DIM   256
#define OUT_DIM  64
#define HCOLS    192   // [hp | lp | i]
#define MAX_NODES 100000
#define MAX_EDGES 3300000

// ---------------- scratch (device globals: no allocations allowed) ----------
__device__ float g_hall[(size_t)MAX_NODES * HCOLS];   // x @ [Whp|Wlp|Wi] + b
__device__ int   g_deg [MAX_NODES];
__device__ int   g_cur [MAX_NODES];                   // scatter cursors
__device__ int   g_rowp[MAX_NODES + 1];               // CSR row pointers (by dst)
__device__ int   g_adj [MAX_EDGES];                   // CSR column (src) indices
__device__ float g_isq [MAX_NODES];                   // 1/sqrt(deg)
__device__ float g_inv [MAX_NODES];                   // 1/deg
__device__ float g_Wall[IN_DIM * HCOLS];
__device__ float g_ball[HCOLS];
__device__ int   g_is64;                              // edge_index dtype flag
__device__ int   g_bsum[128];                         // scan block sums

// ---------------- edge dtype detector (1 warp, parallel loads) ---------------
// int64 view of an int32 buffer packs two indices per word -> values >= 2^32
// unless the high index is 0 (prob 1e-5 each); 32 samples all passing ~ 1e-160.
__global__ void k_detect(const void* __restrict__ ei, int E, int n) {
    const long long* p = (const long long*)ei;
    int lane = threadIdx.x;
    int idx = lane < E ? lane : (E > 0 ? E - 1 : 0);
    long long v = (E > 0) ? p[idx] : -1;
    bool good = (v >= 0 && v < (long long)n);
    unsigned all = __all_sync(0xFFFFFFFFu, good);
    if (lane == 0) g_is64 = all ? 1 : 0;
}

__device__ __forceinline__ int edge_at(const void* ei, size_t idx) {
    if (g_is64) return (int)((const long long*)ei)[idx];
    return ((const int*)ei)[idx];
}

// ---------------- zero deg + cursors (deterministic per launch) --------------
__global__ void k_zero(int n) {
    int i = blockIdx.x * blockDim.x + threadIdx.x;
    if (i < n) { g_deg[i] = 0; g_cur[i] = 0; }
}

// ---------------- pack weights: W_all[256][192], b_all[192] ------------------
__global__ void k_prep_w(const float* __restrict__ Whp, const float* __restrict__ bhp,
                         const float* __restrict__ Wlp, const float* __restrict__ blp,
                         const float* __restrict__ Wi,  const float* __restrict__ bi) {
    int idx = blockIdx.x * blockDim.x + threadIdx.x;
    if (idx < IN_DIM * HCOLS) {
        int k = idx / HCOLS, j = idx % HCOLS;
        float v;
        if      (j < 64)  v = Whp[k * 64 + j];
        else if (j < 128) v = Wlp[k * 64 + (j - 64)];
        else              v = Wi [k * 64 + (j - 128)];
        g_Wall[idx] = v;
    }
    if (idx < HCOLS) {
        g_ball[idx] = (idx < 64) ? bhp[idx] : (idx < 128 ? blp[idx - 64] : bi[idx - 128]);
    }
}

// ---------------- degree count (int atomics, bounds-guarded) -----------------
__global__ void k_deg(const void* __restrict__ ei, int E, int n) {
    int e = blockIdx.x * blockDim.x + threadIdx.x;
    if (e < E) {
        int dst = edge_at(ei, (size_t)E + e);
        if ((unsigned)dst < (unsigned)n) atomicAdd(&g_deg[dst], 1);
    }
}
__global__ void k_degfin(int n) {
    int i = blockIdx.x * blockDim.x + threadIdx.x;
    if (i < n) {
        float d = (float)g_deg[i] + 1.0f;   // self-loop
        g_isq[i] = rsqrtf(d);
        g_inv[i] = 1.0f / d;
    }
}

// ---------------- multi-block scan: deg -> row_ptr ---------------------------
// scan1: per-block inclusive scan of 1024 elems, block total to g_bsum.
__global__ void __launch_bounds__(1024) k_scan1(int n) {
    __shared__ int sh[1024];
    int i = blockIdx.x * 1024 + threadIdx.x;
    sh[threadIdx.x] = (i < n) ? g_deg[i] : 0;
    __syncthreads();
#pragma unroll
    for (int off = 1; off < 1024; off <<= 1) {
        int t = (threadIdx.x >= off) ? sh[threadIdx.x - off] : 0;
        __syncthreads();
        sh[threadIdx.x] += t;
        __syncthreads();
    }
    if (i < n) g_rowp[i + 1] = sh[threadIdx.x];
    if (threadIdx.x == 1023) g_bsum[blockIdx.x] = sh[1023];
}
// scan2: single block inclusive scan of the <=128 block sums.
__global__ void __launch_bounds__(128) k_scan2(int nb) {
    __shared__ int sh[128];
    sh[threadIdx.x] = (threadIdx.x < nb) ? g_bsum[threadIdx.x] : 0;
    __syncthreads();
#pragma unroll
    for (int off = 1; off < 128; off <<= 1) {
        int t = (threadIdx.x >= off) ? sh[threadIdx.x - off] : 0;
        __syncthreads();
        sh[threadIdx.x] += t;
        __syncthreads();
    }
    g_bsum[threadIdx.x] = sh[threadIdx.x];
}
// scan3: add preceding-block offsets.
__global__ void k_scan3(int n) {
    int i = blockIdx.x * blockDim.x + threadIdx.x;
    if (i < n) {
        int b = i >> 10;
        if (b > 0) g_rowp[i + 1] += g_bsum[b - 1];
    }
    if (i == 0) g_rowp[0] = 0;
}

// ---------------- scatter edges into CSR (int cursor atomics, guarded) -------
__global__ void k_scatter(const void* __restrict__ ei, int E, int n) {
    int e = blockIdx.x * blockDim.x + threadIdx.x;
    if (e < E) {
        int src = edge_at(ei, (size_t)e);
        int dst = edge_at(ei, (size_t)E + e);
        if ((unsigned)src < (unsigned)n && (unsigned)dst < (unsigned)n) {
            int pos = g_rowp[dst] + atomicAdd(&g_cur[dst], 1);
            if ((unsigned)pos < (unsigned)MAX_EDGES) g_adj[pos] = src;
        }
    }
}

// ---------------- tf32 tensor-core GEMM: h_all = x @ W_all + b_all -----------
// BM=128, BN=64, BK=32; 256 threads = 8 warps (4x2); warp tile 32x32;
// mma.sync.aligned.m16n8k8.row.col.f32.tf32.tf32.f32, fp32 accumulate.
__device__ __forceinline__ uint32_t f2tf32(float f) {
    uint32_t u;
    asm("cvt.rna.tf32.f32 %0, %1;" : "=r"(u) : "f"(f));
    return u;
}

__global__ void __launch_bounds__(256) k_gemm(const float* __restrict__ x, int M) {
    __shared__ float As[128][36];   // [m][k], pad 36: fragment loads conflict-free
    __shared__ float Bs[32][72];    // [k][n], pad 72: 72k mod 32 = 8k -> conflict-free

    const int tid  = threadIdx.x;
    const int wid  = tid >> 5;
    const int lane = tid & 31;
    const int m0 = blockIdx.x * 128;
    const int n0 = blockIdx.y * 64;
    const int wm = (wid >> 1) * 32;     // warp row offset: 0,32,64,96
    const int wn = (wid & 1) * 32;      // warp col offset: 0,32
    const int grp = lane >> 2;          // 0..7
    const int tig = lane & 3;           // 0..3

    float acc[2][4][4];
#pragma unroll
    for (int mi = 0; mi < 2; mi++)
#pragma unroll
        for (int ni = 0; ni < 4; ni++)
#pragma unroll
            for (int r = 0; r < 4; r++) acc[mi][ni][r] = 0.f;

    for (int k0 = 0; k0 < IN_DIM; k0 += 32) {
        // load A tile: 128x32 = 1024 float4, 4 per thread
#pragma unroll
        for (int r = 0; r < 4; r++) {
            int f = tid + r * 256;
            int row = f >> 3;            // 8 float4 per row
            int col = (f & 7) * 4;
            int m = m0 + row;
            int ms = m < M ? m : M - 1;
            float4 v = *reinterpret_cast<const float4*>(x + (size_t)ms * IN_DIM + k0 + col);
            *reinterpret_cast<float4*>(&As[row][col]) = v;
        }
        // load B tile: 32x64 = 512 float4, 2 per thread
#pragma unroll
        for (int r = 0; r < 2; r++) {
            int f = tid + r * 256;
            int row = f >> 4;            // 16 float4 per row
            int col = (f & 15) * 4;
            float4 w = *reinterpret_cast<const float4*>(g_Wall + (size_t)(k0 + row) * HCOLS + n0 + col);
            *reinterpret_cast<float4*>(&Bs[row][col]) = w;
        }
        __syncthreads();

#pragma unroll
        for (int kk = 0; kk < 4; kk++) {
            const int k8 = kk * 8;
            uint32_t ta[2][4], tb[4][2];
#pragma unroll
            for (int mi = 0; mi < 2; mi++) {
                int row = wm + mi * 16 + grp;
                ta[mi][0] = f2tf32(As[row    ][k8 + tig    ]);
                ta[mi][1] = f2tf32(As[row + 8][k8 + tig    ]);
                ta[mi][2] = f2tf32(As[row    ][k8 + tig + 4]);
                ta[mi][3] = f2tf32(As[row + 8][k8 + tig + 4]);
            }
#pragma unroll
            for (int ni = 0; ni < 4; ni++) {
                int col = wn + ni * 8 + grp;
                tb[ni][0] = f2tf32(Bs[k8 + tig    ][col]);
                tb[ni][1] = f2tf32(Bs[k8 + tig + 4][col]);
            }
#pragma unroll
            for (int mi = 0; mi < 2; mi++)
#pragma unroll
                for (int ni = 0; ni < 4; ni++) {
                    asm volatile(
                        "mma.sync.aligned.m16n8k8.row.col.f32.tf32.tf32.f32 "
                        "{%0,%1,%2,%3}, {%4,%5,%6,%7}, {%8,%9}, {%0,%1,%2,%3};"
                        : "+f"(acc[mi][ni][0]), "+f"(acc[mi][ni][1]),
                          "+f"(acc[mi][ni][2]), "+f"(acc[mi][ni][3])
                        : "r"(ta[mi][0]), "r"(ta[mi][1]), "r"(ta[mi][2]), "r"(ta[mi][3]),
                          "r"(tb[ni][0]), "r"(tb[ni][1]));
                }
        }
        __syncthreads();
    }

    // epilogue: c0,c1 -> (row, col..col+1); c2,c3 -> (row+8, col..col+1)
#pragma unroll
    for (int mi = 0; mi < 2; mi++) {
#pragma unroll
        for (int ni = 0; ni < 4; ni++) {
            int col = n0 + wn + ni * 8 + 2 * tig;
            float b0 = g_ball[col], b1 = g_ball[col + 1];
            int row = m0 + wm + mi * 16 + grp;
            if (row < M) {
                float2 o = make_float2(acc[mi][ni][0] + b0, acc[mi][ni][1] + b1);
                *reinterpret_cast<float2*>(g_hall + (size_t)row * HCOLS + col) = o;
            }
            if (row + 8 < M) {
                float2 o = make_float2(acc[mi][ni][2] + b0, acc[mi][ni][3] + b1);
                *reinterpret_cast<float2*>(g_hall + (size_t)(row + 8) * HCOLS + col) = o;
            }
        }
    }
}

// ---------------- fused gather + epilogue (warp per node, NO float atomics) --
__global__ void __launch_bounds__(256) k_final(
    const float* __restrict__ wgh, const float* __restrict__ bgh,
    const float* __restrict__ wgl, const float* __restrict__ bgl,
    const float* __restrict__ wgi, const float* __restrict__ bgi,
    float* __restrict__ out, int n)
{
    __shared__ float sagg[8][128];
    int wslot = threadIdx.x >> 5;
    int node = blockIdx.x * 8 + wslot;
    int lane = threadIdx.x & 31;
    if (node >= n) return;

    int beg = g_rowp[node], end = g_rowp[node + 1];
    float isqd = g_isq[node];

    float4 acc = make_float4(0.f, 0.f, 0.f, 0.f);
    for (int p = beg; p < end; p++) {
        int src = g_adj[p];                            // warp-broadcast load
        float w = isqd * g_isq[src];
        float4 v = *reinterpret_cast<const float4*>(g_hall + (size_t)src * HCOLS + lane * 4);
        acc.x += w * v.x; acc.y += w * v.y; acc.z += w * v.z; acc.w += w * v.w;
    }
    *reinterpret_cast<float4*>(&sagg[wslot][lane * 4]) = acc;
    __syncwarp();

    const float* hrow = g_hall + (size_t)node * HCOLS;
    const float* arow = sagg[wslot];
    float inv = g_inv[node];

    float Hhp[2], Hlp[2], Hi[2];
    float gh = 0.f, gl = 0.f, gi = 0.f;
#pragma unroll
    for (int t = 0; t < 2; t++) {
        int d = lane + t * 32;
        float hp = hrow[d], lp = hrow[64 + d], hi = hrow[128 + d];
        float ah = arow[d], al = arow[64 + d];
        Hhp[t] = fmaxf(hp - (ah + inv * hp), 0.f);   // HP = relu(h - A_hat h)
        Hlp[t] = fmaxf(al + inv * lp, 0.f);          // LP = relu(A_hat h)
        Hi [t] = fmaxf(hi, 0.f);                     // I  = relu(h)
        gh += Hhp[t] * wgh[d];
        gl += Hlp[t] * wgl[d];
        gi += Hi [t] * wgi[d];
    }
#pragma unroll
    for (int o = 16; o > 0; o >>= 1) {
        gh += __shfl_xor_sync(0xFFFFFFFFu, gh, o);
        gl += __shfl_xor_sync(0xFFFFFFFFu, gl, o);
        gi += __shfl_xor_sync(0xFFFFFFFFu, gi, o);
    }
    gh += bgh[0]; gl += bgl[0]; gi += bgi[0];

    float o0 = gh * Hhp[0] + gl * Hlp[0] + gi * Hi[0];
    float o1 = gh * Hhp[1] + gl * Hlp[1] + gi * Hi[1];

    float m = fmaxf(o0, o1);
#pragma unroll
    for (int o = 16; o > 0; o >>= 1) m = fmaxf(m, __shfl_xor_sync(0xFFFFFFFFu, m, o));
    float s = expf(o0 - m) + expf(o1 - m);
#pragma unroll
    for (int o = 16; o > 0; o >>= 1) s += __shfl_xor_sync(0xFFFFFFFFu, s, o);
    float lse = m + logf(s);

    out[(size_t)node * 64 + lane]      = o0 - lse;
    out[(size_t)node * 64 + lane + 32] = o1 - lse;
}

// ---------------- host launch ------------------------------------------------
extern "C" void kernel_launch(void* const* d_in, const int* in_sizes, int n_in,
                              void* d_out, int out_size) {
    const float* x  = (const float*)d_in[0];
    const void*  ei = d_in[1];                      // int32 or int64; detected on-device
    const float* Whp = (const float*)d_in[2];
    const float* bhp = (const float*)d_in[3];
    const float* Wlp = (const float*)d_in[4];
    const float* blp = (const float*)d_in[5];
    const float* Wi  = (const float*)d_in[6];
    const float* bi  = (const float*)d_in[7];
    const float* wgh = (const float*)d_in[8];
    const float* bgh = (const float*)d_in[9];
    const float* wgl = (const float*)d_in[10];
    const float* bgl = (const float*)d_in[11];
    const float* wgi = (const float*)d_in[12];
    const float* bgi = (const float*)d_in[13];
    float* out = (float*)d_out;

    int n = in_sizes[0] / IN_DIM;   // 100000
    int E = in_sizes[1] / 2;        // 3200000
    int nb = (n + 1023) / 1024;     // scan blocks (<=128)

    k_detect<<<1, 32>>>(ei, E, n);
    k_zero<<<(n + 255) / 256, 256>>>(n);
    k_prep_w<<<(IN_DIM * HCOLS + 255) / 256, 256>>>(Whp, bhp, Wlp, blp, Wi, bi);
    k_deg<<<(E + 255) / 256, 256>>>(ei, E, n);
    k_degfin<<<(n + 255) / 256, 256>>>(n);
    k_scan1<<<nb, 1024>>>(n);
    k_scan2<<<1, 128>>>(nb);
    k_scan3<<<(n + 255) / 256, 256>>>(n);
    k_scatter<<<(E + 255) / 256, 256>>>(ei, E, n);
    k_gemm<<<dim3((n + 127) / 128, 3), 256>>>(x, n);
    k_final<<<(n + 7) / 8, 256>>>(wgh, bgh, wgl, bgl, wgi, bgi, out, n);
}

// round 8
// speedup vs baseline: 1.7374x; 1.0439x over previous
#include <cuda_runtime.h>
#include <cuda_fp16.h>
#include <cstdint>

#define IN_DIM   256
#define OUT_DIM  64
#define HCOLS    192   // [hp | lp | i]
#define MAX_NODES 100000
#define MAX_EDGES 3300000

// ---------------- scratch (device globals: no allocations allowed) ----------
__device__ float   g_hall[(size_t)MAX_NODES * HCOLS];  // fp32 h (all paths)
__device__ __half2 g_hlp [(size_t)MAX_NODES * 64];     // fp16 mirror of cols 0..127 (gather)
__device__ int     g_deg [MAX_NODES];
__device__ int     g_cur [MAX_NODES];
__device__ int     g_rowp[MAX_NODES + 1];
__device__ int     g_adj [MAX_EDGES];
__device__ float   g_isq [MAX_NODES];
__device__ float   g_inv [MAX_NODES];
__device__ float   g_Wall[IN_DIM * HCOLS];
__device__ float   g_ball[HCOLS];
__device__ int     g_is64;
__device__ int     g_bsum[128];

// ---------------- edge dtype detector (1 warp) -------------------------------
__global__ void k_detect(const void* __restrict__ ei, int E, int n) {
    const long long* p = (const long long*)ei;
    int lane = threadIdx.x;
    int idx = lane < E ? lane : (E > 0 ? E - 1 : 0);
    long long v = (E > 0) ? p[idx] : -1;
    bool good = (v >= 0 && v < (long long)n);
    unsigned all = __all_sync(0xFFFFFFFFu, good);
    if (lane == 0) g_is64 = all ? 1 : 0;
}

__device__ __forceinline__ int edge_at(const void* ei, size_t idx) {
    if (g_is64) return (int)((const long long*)ei)[idx];
    return ((const int*)ei)[idx];
}

// ---------------- zero deg + cursors -----------------------------------------
__global__ void k_zero(int n) {
    int i = blockIdx.x * blockDim.x + threadIdx.x;
    if (i < n) { g_deg[i] = 0; g_cur[i] = 0; }
}

// ---------------- pack weights -----------------------------------------------
__global__ void k_prep_w(const float* __restrict__ Whp, const float* __restrict__ bhp,
                         const float* __restrict__ Wlp, const float* __restrict__ blp,
                         const float* __restrict__ Wi,  const float* __restrict__ bi) {
    int idx = blockIdx.x * blockDim.x + threadIdx.x;
    if (idx < IN_DIM * HCOLS) {
        int k = idx / HCOLS, j = idx % HCOLS;
        float v;
        if      (j < 64)  v = Whp[k * 64 + j];
        else if (j < 128) v = Wlp[k * 64 + (j - 64)];
        else              v = Wi [k * 64 + (j - 128)];
        g_Wall[idx] = v;
    }
    if (idx < HCOLS) {
        g_ball[idx] = (idx < 64) ? bhp[idx] : (idx < 128 ? blp[idx - 64] : bi[idx - 128]);
    }
}

// ---------------- degree count -----------------------------------------------
__global__ void k_deg(const void* __restrict__ ei, int E, int n) {
    int e = blockIdx.x * blockDim.x + threadIdx.x;
    if (e < E) {
        int dst = edge_at(ei, (size_t)E + e);
        if ((unsigned)dst < (unsigned)n) atomicAdd(&g_deg[dst], 1);
    }
}
__global__ void k_degfin(int n) {
    int i = blockIdx.x * blockDim.x + threadIdx.x;
    if (i < n) {
        float d = (float)g_deg[i] + 1.0f;
        g_isq[i] = rsqrtf(d);
        g_inv[i] = 1.0f / d;
    }
}

// ---------------- multi-block scan: deg -> row_ptr ---------------------------
__global__ void __launch_bounds__(1024) k_scan1(int n) {
    __shared__ int sh[1024];
    int i = blockIdx.x * 1024 + threadIdx.x;
    sh[threadIdx.x] = (i < n) ? g_deg[i] : 0;
    __syncthreads();
#pragma unroll
    for (int off = 1; off < 1024; off <<= 1) {
        int t = (threadIdx.x >= off) ? sh[threadIdx.x - off] : 0;
        __syncthreads();
        sh[threadIdx.x] += t;
        __syncthreads();
    }
    if (i < n) g_rowp[i + 1] = sh[threadIdx.x];
    if (threadIdx.x == 1023) g_bsum[blockIdx.x] = sh[1023];
}
__global__ void __launch_bounds__(128) k_scan2(int nb) {
    __shared__ int sh[128];
    sh[threadIdx.x] = (threadIdx.x < nb) ? g_bsum[threadIdx.x] : 0;
    __syncthreads();
#pragma unroll
    for (int off = 1; off < 128; off <<= 1) {
        int t = (threadIdx.x >= off) ? sh[threadIdx.x - off] : 0;
        __syncthreads();
        sh[threadIdx.x] += t;
        __syncthreads();
    }
    g_bsum[threadIdx.x] = sh[threadIdx.x];
}
__global__ void k_scan3(int n) {
    int i = blockIdx.x * blockDim.x + threadIdx.x;
    if (i < n) {
        int b = i >> 10;
        if (b > 0) g_rowp[i + 1] += g_bsum[b - 1];
    }
    if (i == 0) g_rowp[0] = 0;
}

// ---------------- scatter edges into CSR -------------------------------------
__global__ void k_scatter(const void* __restrict__ ei, int E, int n) {
    int e = blockIdx.x * blockDim.x + threadIdx.x;
    if (e < E) {
        int src = edge_at(ei, (size_t)e);
        int dst = edge_at(ei, (size_t)E + e);
        if ((unsigned)src < (unsigned)n && (unsigned)dst < (unsigned)n) {
            int pos = g_rowp[dst] + atomicAdd(&g_cur[dst], 1);
            if ((unsigned)pos < (unsigned)MAX_EDGES) g_adj[pos] = src;
        }
    }
}

// ---------------- tf32 GEMM: BM=128, BN=192 (all cols), BK=32; 512 thr -------
__device__ __forceinline__ uint32_t f2tf32(float f) {
    uint32_t u;
    asm("cvt.rna.tf32.f32 %0, %1;" : "=r"(u) : "f"(f));
    return u;
}

__global__ void __launch_bounds__(512) k_gemm(const float* __restrict__ x, int M) {
    __shared__ float As[128][36];   // stride 36: grp*4+tig -> 32 distinct banks
    __shared__ float Bs[32][200];   // stride 200 (mod 32 = 8): tig*8+grp distinct

    const int tid  = threadIdx.x;
    const int wid  = tid >> 5;
    const int lane = tid & 31;
    const int m0 = blockIdx.x * 128;
    const int wm = (wid >> 2) * 32;     // 0,32,64,96
    const int wn = (wid & 3) * 48;      // 0,48,96,144
    const int grp = lane >> 2;          // 0..7
    const int tig = lane & 3;           // 0..3

    float acc[2][6][4];
#pragma unroll
    for (int mi = 0; mi < 2; mi++)
#pragma unroll
        for (int ni = 0; ni < 6; ni++)
#pragma unroll
            for (int r = 0; r < 4; r++) acc[mi][ni][r] = 0.f;

    for (int k0 = 0; k0 < IN_DIM; k0 += 32) {
        // A tile: 128x32 = 1024 float4, 2 per thread
#pragma unroll
        for (int r = 0; r < 2; r++) {
            int f = tid + r * 512;
            int row = f >> 3;
            int col = (f & 7) * 4;
            int m = m0 + row;
            int ms = m < M ? m : M - 1;
            float4 v = *reinterpret_cast<const float4*>(x + (size_t)ms * IN_DIM + k0 + col);
            *reinterpret_cast<float4*>(&As[row][col]) = v;
        }
        // B tile: 32x192 = 1536 float4, 3 per thread
#pragma unroll
        for (int r = 0; r < 3; r++) {
            int f = tid + r * 512;
            int row = f / 48;
            int col = (f % 48) * 4;
            float4 w = *reinterpret_cast<const float4*>(g_Wall + (size_t)(k0 + row) * HCOLS + col);
            *reinterpret_cast<float4*>(&Bs[row][col]) = w;
        }
        __syncthreads();

#pragma unroll
        for (int kk = 0; kk < 4; kk++) {
            const int k8 = kk * 8;
            uint32_t ta[2][4], tb[6][2];
#pragma unroll
            for (int mi = 0; mi < 2; mi++) {
                int row = wm + mi * 16 + grp;
                ta[mi][0] = f2tf32(As[row    ][k8 + tig    ]);
                ta[mi][1] = f2tf32(As[row + 8][k8 + tig    ]);
                ta[mi][2] = f2tf32(As[row    ][k8 + tig + 4]);
                ta[mi][3] = f2tf32(As[row + 8][k8 + tig + 4]);
            }
#pragma unroll
            for (int ni = 0; ni < 6; ni++) {
                int col = wn + ni * 8 + grp;
                tb[ni][0] = f2tf32(Bs[k8 + tig    ][col]);
                tb[ni][1] = f2tf32(Bs[k8 + tig + 4][col]);
            }
#pragma unroll
            for (int mi = 0; mi < 2; mi++)
#pragma unroll
                for (int ni = 0; ni < 6; ni++) {
                    asm volatile(
                        "mma.sync.aligned.m16n8k8.row.col.f32.tf32.tf32.f32 "
                        "{%0,%1,%2,%3}, {%4,%5,%6,%7}, {%8,%9}, {%0,%1,%2,%3};"
                        : "+f"(acc[mi][ni][0]), "+f"(acc[mi][ni][1]),
                          "+f"(acc[mi][ni][2]), "+f"(acc[mi][ni][3])
                        : "r"(ta[mi][0]), "r"(ta[mi][1]), "r"(ta[mi][2]), "r"(ta[mi][3]),
                          "r"(tb[ni][0]), "r"(tb[ni][1]));
                }
        }
        __syncthreads();
    }

    // epilogue: fp32 to g_hall; cols<128 also packed fp16 to g_hlp
#pragma unroll
    for (int mi = 0; mi < 2; mi++) {
#pragma unroll
        for (int ni = 0; ni < 6; ni++) {
            int col = wn + ni * 8 + 2 * tig;
            float b0 = g_ball[col], b1 = g_ball[col + 1];
            int row = m0 + wm + mi * 16 + grp;
            if (row < M) {
                float2 o = make_float2(acc[mi][ni][0] + b0, acc[mi][ni][1] + b1);
                *reinterpret_cast<float2*>(g_hall + (size_t)row * HCOLS + col) = o;
                if (col < 128) g_hlp[(size_t)row * 64 + (col >> 1)] = __float22half2_rn(o);
            }
            if (row + 8 < M) {
                float2 o = make_float2(acc[mi][ni][2] + b0, acc[mi][ni][3] + b1);
                *reinterpret_cast<float2*>(g_hall + (size_t)(row + 8) * HCOLS + col) = o;
                if (col < 128) g_hlp[(size_t)(row + 8) * 64 + (col >> 1)] = __float22half2_rn(o);
            }
        }
    }
}

// ---------------- fused gather (fp16 reads, fp32 accum) + epilogue -----------
__global__ void __launch_bounds__(256) k_final(
    const float* __restrict__ wgh, const float* __restrict__ bgh,
    const float* __restrict__ wgl, const float* __restrict__ bgl,
    const float* __restrict__ wgi, const float* __restrict__ bgi,
    float* __restrict__ out, int n)
{
    __shared__ float sagg[8][128];
    int wslot = threadIdx.x >> 5;
    int node = blockIdx.x * 8 + wslot;
    int lane = threadIdx.x & 31;
    if (node >= n) return;

    int beg = g_rowp[node], end = g_rowp[node + 1];
    float isqd = g_isq[node];

    // lane owns cols [4*lane, 4*lane+4) = half2 indices 2*lane, 2*lane+1
    float4 acc = make_float4(0.f, 0.f, 0.f, 0.f);
    for (int p = beg; p < end; p++) {
        int src = g_adj[p];                            // warp-broadcast load
        float w = isqd * g_isq[src];
        uint2 raw = *reinterpret_cast<const uint2*>(g_hlp + (size_t)src * 64 + 2 * lane);
        float2 f0 = __half22float2(*reinterpret_cast<__half2*>(&raw.x));
        float2 f1 = __half22float2(*reinterpret_cast<__half2*>(&raw.y));
        acc.x += w * f0.x; acc.y += w * f0.y; acc.z += w * f1.x; acc.w += w * f1.y;
    }
    *reinterpret_cast<float4*>(&sagg[wslot][lane * 4]) = acc;
    __syncwarp();

    const float* hrow = g_hall + (size_t)node * HCOLS;
    const float* arow = sagg[wslot];
    float inv = g_inv[node];

    float Hhp[2], Hlp[2], Hi[2];
    float gh = 0.f, gl = 0.f, gi = 0.f;
#pragma unroll
    for (int t = 0; t < 2; t++) {
        int d = lane + t * 32;
        float hp = hrow[d], lp = hrow[64 + d], hi = hrow[128 + d];
        float ah = arow[d], al = arow[64 + d];
        Hhp[t] = fmaxf(hp - (ah + inv * hp), 0.f);   // HP = relu(h - A_hat h)
        Hlp[t] = fmaxf(al + inv * lp, 0.f);          // LP = relu(A_hat h)
        Hi [t] = fmaxf(hi, 0.f);                     // I  = relu(h)
        gh += Hhp[t] * wgh[d];
        gl += Hlp[t] * wgl[d];
        gi += Hi [t] * wgi[d];
    }
#pragma unroll
    for (int o = 16; o > 0; o >>= 1) {
        gh += __shfl_xor_sync(0xFFFFFFFFu, gh, o);
        gl += __shfl_xor_sync(0xFFFFFFFFu, gl, o);
        gi += __shfl_xor_sync(0xFFFFFFFFu, gi, o);
    }
    gh += bgh[0]; gl += bgl[0]; gi += bgi[0];

    float o0 = gh * Hhp[0] + gl * Hlp[0] + gi * Hi[0];
    float o1 = gh * Hhp[1] + gl * Hlp[1] + gi * Hi[1];

    float m = fmaxf(o0, o1);
#pragma unroll
    for (int o = 16; o > 0; o >>= 1) m = fmaxf(m, __shfl_xor_sync(0xFFFFFFFFu, m, o));
    float s = expf(o0 - m) + expf(o1 - m);
#pragma unroll
    for (int o = 16; o > 0; o >>= 1) s += __shfl_xor_sync(0xFFFFFFFFu, s, o);
    float lse = m + logf(s);

    out[(size_t)node * 64 + lane]      = o0 - lse;
    out[(size_t)node * 64 + lane + 32] = o1 - lse;
}

// ---------------- host launch ------------------------------------------------
extern "C" void kernel_launch(void* const* d_in, const int* in_sizes, int n_in,
                              void* d_out, int out_size) {
    const float* x  = (const float*)d_in[0];
    const void*  ei = d_in[1];
    const float* Whp = (const float*)d_in[2];
    const float* bhp = (const float*)d_in[3];
    const float* Wlp = (const float*)d_in[4];
    const float* blp = (const float*)d_in[5];
    const float* Wi  = (const float*)d_in[6];
    const float* bi  = (const float*)d_in[7];
    const float* wgh = (const float*)d_in[8];
    const float* bgh = (const float*)d_in[9];
    const float* wgl = (const float*)d_in[10];
    const float* bgl = (const float*)d_in[11];
    const float* wgi = (const float*)d_in[12];
    const float* bgi = (const float*)d_in[13];
    float* out = (float*)d_out;

    int n = in_sizes[0] / IN_DIM;   // 100000
    int E = in_sizes[1] / 2;        // 3200000
    int nb = (n + 1023) / 1024;     // scan blocks (<=128)

    k_detect<<<1, 32>>>(ei, E, n);
    k_zero<<<(n + 255) / 256, 256>>>(n);
    k_prep_w<<<(IN_DIM * HCOLS + 255) / 256, 256>>>(Whp, bhp, Wlp, blp, Wi, bi);
    k_deg<<<(E + 255) / 256, 256>>>(ei, E, n);
    k_degfin<<<(n + 255) / 256, 256>>>(n);
    k_scan1<<<nb, 1024>>>(n);
    k_scan2<<<1, 128>>>(nb);
    k_scan3<<<(n + 255) / 256, 256>>>(n);
    k_scatter<<<(E + 255) / 256, 256>>>(ei, E, n);
    k_gemm<<<(n + 127) / 128, 512>>>(x, n);
    k_final<<<(n + 7) / 8, 256>>>(wgh, bgh, wgl, bgl, wgi, bgi, out, n);
}

// round 9
// speedup vs baseline: 1.8258x; 1.0509x over previous
#include <cuda_runtime.h>
#include <cuda_fp16.h>
#include <cstdint>

#define IN_DIM   256
#define OUT_DIM  64
#define HCOLS    192   // [hp | lp | i]
#define MAX_NODES 100000
#define MAX_EDGES 3300000

// ---------------- scratch (device globals: no allocations allowed) ----------
__device__ float   g_hall[(size_t)MAX_NODES * HCOLS];  // fp32 h (all paths)
__device__ __half2 g_hlp [(size_t)MAX_NODES * 64];     // fp16 mirror of cols 0..127 (gather)
__device__ int     g_deg [MAX_NODES];
__device__ int     g_cur [MAX_NODES];
__device__ int     g_rowp[MAX_NODES + 1];
__device__ int     g_adj [MAX_EDGES];
__device__ float   g_isq [MAX_NODES];
__device__ float   g_inv [MAX_NODES];
__device__ float   g_Wall[IN_DIM * HCOLS];
__device__ float   g_ball[HCOLS];
__device__ int     g_is64;
__device__ int     g_bsum[128];

// ---------------- edge dtype detector (1 warp) -------------------------------
__global__ void k_detect(const void* __restrict__ ei, int E, int n) {
    const long long* p = (const long long*)ei;
    int lane = threadIdx.x;
    int idx = lane < E ? lane : (E > 0 ? E - 1 : 0);
    long long v = (E > 0) ? p[idx] : -1;
    bool good = (v >= 0 && v < (long long)n);
    unsigned all = __all_sync(0xFFFFFFFFu, good);
    if (lane == 0) g_is64 = all ? 1 : 0;
}

__device__ __forceinline__ int edge_at(const void* ei, size_t idx) {
    if (g_is64) return (int)((const long long*)ei)[idx];
    return ((const int*)ei)[idx];
}

// ---------------- zero deg + cursors -----------------------------------------
__global__ void k_zero(int n) {
    int i = blockIdx.x * blockDim.x + threadIdx.x;
    if (i < n) { g_deg[i] = 0; g_cur[i] = 0; }
}

// ---------------- pack weights -----------------------------------------------
__global__ void k_prep_w(const float* __restrict__ Whp, const float* __restrict__ bhp,
                         const float* __restrict__ Wlp, const float* __restrict__ blp,
                         const float* __restrict__ Wi,  const float* __restrict__ bi) {
    int idx = blockIdx.x * blockDim.x + threadIdx.x;
    if (idx < IN_DIM * HCOLS) {
        int k = idx / HCOLS, j = idx % HCOLS;
        float v;
        if      (j < 64)  v = Whp[k * 64 + j];
        else if (j < 128) v = Wlp[k * 64 + (j - 64)];
        else              v = Wi [k * 64 + (j - 128)];
        g_Wall[idx] = v;
    }
    if (idx < HCOLS) {
        g_ball[idx] = (idx < 64) ? bhp[idx] : (idx < 128 ? blp[idx - 64] : bi[idx - 128]);
    }
}

// ---------------- degree count -----------------------------------------------
__global__ void k_deg(const void* __restrict__ ei, int E, int n) {
    int e = blockIdx.x * blockDim.x + threadIdx.x;
    if (e < E) {
        int dst = edge_at(ei, (size_t)E + e);
        if ((unsigned)dst < (unsigned)n) atomicAdd(&g_deg[dst], 1);
    }
}

// ---------------- multi-block scan: deg -> row_ptr ---------------------------
__global__ void __launch_bounds__(1024) k_scan1(int n) {
    __shared__ int sh[1024];
    int i = blockIdx.x * 1024 + threadIdx.x;
    sh[threadIdx.x] = (i < n) ? g_deg[i] : 0;
    __syncthreads();
#pragma unroll
    for (int off = 1; off < 1024; off <<= 1) {
        int t = (threadIdx.x >= off) ? sh[threadIdx.x - off] : 0;
        __syncthreads();
        sh[threadIdx.x] += t;
        __syncthreads();
    }
    if (i < n) g_rowp[i + 1] = sh[threadIdx.x];
    if (threadIdx.x == 1023) g_bsum[blockIdx.x] = sh[1023];
}
__global__ void __launch_bounds__(128) k_scan2(int nb) {
    __shared__ int sh[128];
    sh[threadIdx.x] = (threadIdx.x < nb) ? g_bsum[threadIdx.x] : 0;
    __syncthreads();
#pragma unroll
    for (int off = 1; off < 128; off <<= 1) {
        int t = (threadIdx.x >= off) ? sh[threadIdx.x - off] : 0;
        __syncthreads();
        sh[threadIdx.x] += t;
        __syncthreads();
    }
    g_bsum[threadIdx.x] = sh[threadIdx.x];
}
// scan3 + degfin fused
__global__ void k_scan3(int n) {
    int i = blockIdx.x * blockDim.x + threadIdx.x;
    if (i < n) {
        int b = i >> 10;
        if (b > 0) g_rowp[i + 1] += g_bsum[b - 1];
        float d = (float)g_deg[i] + 1.0f;   // self-loop
        g_isq[i] = rsqrtf(d);
        g_inv[i] = 1.0f / d;
    }
    if (i == 0) g_rowp[0] = 0;
}

// ---------------- scatter edges into CSR -------------------------------------
__global__ void k_scatter(const void* __restrict__ ei, int E, int n) {
    int e = blockIdx.x * blockDim.x + threadIdx.x;
    if (e < E) {
        int src = edge_at(ei, (size_t)e);
        int dst = edge_at(ei, (size_t)E + e);
        if ((unsigned)src < (unsigned)n && (unsigned)dst < (unsigned)n) {
            int pos = g_rowp[dst] + atomicAdd(&g_cur[dst], 1);
            if ((unsigned)pos < (unsigned)MAX_EDGES) g_adj[pos] = src;
        }
    }
}

// ---------------- tf32 GEMM, cp.async double-buffered ------------------------
// BM=128, BN=192, BK=32; 512 thr = 16 warps (4x4); warp tile 32x48.
__device__ __forceinline__ uint32_t f2tf32(float f) {
    uint32_t u;
    asm("cvt.rna.tf32.f32 %0, %1;" : "=r"(u) : "f"(f));
    return u;
}
__device__ __forceinline__ void cp16(void* smem, const void* gmem) {
    uint32_t s = (uint32_t)__cvta_generic_to_shared(smem);
    asm volatile("cp.async.cg.shared.global [%0], [%1], 16;" :: "r"(s), "l"(gmem));
}

#define AS_STRIDE 36
#define BS_STRIDE 200
#define AS_ELEMS (128 * AS_STRIDE)       // 4608
#define BS_ELEMS (32 * BS_STRIDE)        // 6400
#define GEMM_SMEM ((2 * AS_ELEMS + 2 * BS_ELEMS) * 4)   // 88064 bytes

__global__ void __launch_bounds__(512) k_gemm(const float* __restrict__ x, int M) {
    extern __shared__ float smem[];
    float* As[2] = { smem, smem + AS_ELEMS };
    float* Bs[2] = { smem + 2 * AS_ELEMS, smem + 2 * AS_ELEMS + BS_ELEMS };

    const int tid  = threadIdx.x;
    const int wid  = tid >> 5;
    const int lane = tid & 31;
    const int m0 = blockIdx.x * 128;
    const int wm = (wid >> 2) * 32;
    const int wn = (wid & 3) * 48;
    const int grp = lane >> 2;
    const int tig = lane & 3;

    // load mappings (per thread): A 2 float4, B 3 float4
    const int arow0 = tid >> 3,        acol = (tid & 7) * 4;
    const int brow[3] = { tid / 48, (tid + 512) / 48, (tid + 1024) / 48 };
    const int bcol[3] = { (tid % 48) * 4, ((tid + 512) % 48) * 4, ((tid + 1024) % 48) * 4 };

    auto load_stage = [&](int buf, int k0) {
#pragma unroll
        for (int r = 0; r < 2; r++) {
            int row = arow0 + r * 64;
            int m = m0 + row;
            int ms = m < M ? m : M - 1;
            cp16(&As[buf][row * AS_STRIDE + acol], x + (size_t)ms * IN_DIM + k0 + acol);
        }
#pragma unroll
        for (int r = 0; r < 3; r++) {
            cp16(&Bs[buf][brow[r] * BS_STRIDE + bcol[r]],
                 g_Wall + (size_t)(k0 + brow[r]) * HCOLS + bcol[r]);
        }
        asm volatile("cp.async.commit_group;");
    };

    float acc[2][6][4];
#pragma unroll
    for (int mi = 0; mi < 2; mi++)
#pragma unroll
        for (int ni = 0; ni < 6; ni++)
#pragma unroll
            for (int r = 0; r < 4; r++) acc[mi][ni][r] = 0.f;

    load_stage(0, 0);

    const int NIT = IN_DIM / 32;   // 8
    for (int it = 0; it < NIT; it++) {
        int buf = it & 1;
        if (it + 1 < NIT) {
            load_stage(buf ^ 1, (it + 1) * 32);
            asm volatile("cp.async.wait_group 1;");
        } else {
            asm volatile("cp.async.wait_group 0;");
        }
        __syncthreads();

        const float* A = As[buf];
        const float* B = Bs[buf];
#pragma unroll
        for (int kk = 0; kk < 4; kk++) {
            const int k8 = kk * 8;
            uint32_t ta[2][4], tb[6][2];
#pragma unroll
            for (int mi = 0; mi < 2; mi++) {
                int row = wm + mi * 16 + grp;
                ta[mi][0] = f2tf32(A[(row    ) * AS_STRIDE + k8 + tig    ]);
                ta[mi][1] = f2tf32(A[(row + 8) * AS_STRIDE + k8 + tig    ]);
                ta[mi][2] = f2tf32(A[(row    ) * AS_STRIDE + k8 + tig + 4]);
                ta[mi][3] = f2tf32(A[(row + 8) * AS_STRIDE + k8 + tig + 4]);
            }
#pragma unroll
            for (int ni = 0; ni < 6; ni++) {
                int col = wn + ni * 8 + grp;
                tb[ni][0] = f2tf32(B[(k8 + tig    ) * BS_STRIDE + col]);
                tb[ni][1] = f2tf32(B[(k8 + tig + 4) * BS_STRIDE + col]);
            }
#pragma unroll
            for (int mi = 0; mi < 2; mi++)
#pragma unroll
                for (int ni = 0; ni < 6; ni++) {
                    asm volatile(
                        "mma.sync.aligned.m16n8k8.row.col.f32.tf32.tf32.f32 "
                        "{%0,%1,%2,%3}, {%4,%5,%6,%7}, {%8,%9}, {%0,%1,%2,%3};"
                        : "+f"(acc[mi][ni][0]), "+f"(acc[mi][ni][1]),
                          "+f"(acc[mi][ni][2]), "+f"(acc[mi][ni][3])
                        : "r"(ta[mi][0]), "r"(ta[mi][1]), "r"(ta[mi][2]), "r"(ta[mi][3]),
                          "r"(tb[ni][0]), "r"(tb[ni][1]));
                }
        }
        __syncthreads();
    }

    // epilogue: fp32 to g_hall; cols<128 also packed fp16 to g_hlp
#pragma unroll
    for (int mi = 0; mi < 2; mi++) {
#pragma unroll
        for (int ni = 0; ni < 6; ni++) {
            int col = wn + ni * 8 + 2 * tig;
            float b0 = g_ball[col], b1 = g_ball[col + 1];
            int row = m0 + wm + mi * 16 + grp;
            if (row < M) {
                float2 o = make_float2(acc[mi][ni][0] + b0, acc[mi][ni][1] + b1);
                *reinterpret_cast<float2*>(g_hall + (size_t)row * HCOLS + col) = o;
                if (col < 128) g_hlp[(size_t)row * 64 + (col >> 1)] = __float22half2_rn(o);
            }
            if (row + 8 < M) {
                float2 o = make_float2(acc[mi][ni][2] + b0, acc[mi][ni][3] + b1);
                *reinterpret_cast<float2*>(g_hall + (size_t)(row + 8) * HCOLS + col) = o;
                if (col < 128) g_hlp[(size_t)(row + 8) * 64 + (col >> 1)] = __float22half2_rn(o);
            }
        }
    }
}

// ---------------- fused gather (fp16, unroll-4 MLP) + epilogue ---------------
__global__ void __launch_bounds__(256) k_final(
    const float* __restrict__ wgh, const float* __restrict__ bgh,
    const float* __restrict__ wgl, const float* __restrict__ bgl,
    const float* __restrict__ wgi, const float* __restrict__ bgi,
    float* __restrict__ out, int n)
{
    __shared__ float sagg[8][128];
    int wslot = threadIdx.x >> 5;
    int node = blockIdx.x * 8 + wslot;
    int lane = threadIdx.x & 31;
    if (node >= n) return;

    int beg = g_rowp[node], end = g_rowp[node + 1];
    float isqd = g_isq[node];

    float4 acc = make_float4(0.f, 0.f, 0.f, 0.f);
    int p = beg;
    for (; p + 4 <= end; p += 4) {
        int s0 = g_adj[p], s1 = g_adj[p + 1], s2 = g_adj[p + 2], s3 = g_adj[p + 3];
        float w0 = isqd * g_isq[s0], w1 = isqd * g_isq[s1];
        float w2 = isqd * g_isq[s2], w3 = isqd * g_isq[s3];
        uint2 r0 = *reinterpret_cast<const uint2*>(g_hlp + (size_t)s0 * 64 + 2 * lane);
        uint2 r1 = *reinterpret_cast<const uint2*>(g_hlp + (size_t)s1 * 64 + 2 * lane);
        uint2 r2 = *reinterpret_cast<const uint2*>(g_hlp + (size_t)s2 * 64 + 2 * lane);
        uint2 r3 = *reinterpret_cast<const uint2*>(g_hlp + (size_t)s3 * 64 + 2 * lane);
#define ACCUM(rr, ww) { \
        float2 f0 = __half22float2(*reinterpret_cast<__half2*>(&rr.x)); \
        float2 f1 = __half22float2(*reinterpret_cast<__half2*>(&rr.y)); \
        acc.x += ww * f0.x; acc.y += ww * f0.y; acc.z += ww * f1.x; acc.w += ww * f1.y; }
        ACCUM(r0, w0) ACCUM(r1, w1) ACCUM(r2, w2) ACCUM(r3, w3)
    }
    for (; p < end; p++) {
        int src = g_adj[p];
        float w = isqd * g_isq[src];
        uint2 raw = *reinterpret_cast<const uint2*>(g_hlp + (size_t)src * 64 + 2 * lane);
        ACCUM(raw, w)
    }
#undef ACCUM
    *reinterpret_cast<float4*>(&sagg[wslot][lane * 4]) = acc;
    __syncwarp();

    const float* hrow = g_hall + (size_t)node * HCOLS;
    const float* arow = sagg[wslot];
    float inv = g_inv[node];

    float Hhp[2], Hlp[2], Hi[2];
    float gh = 0.f, gl = 0.f, gi = 0.f;
#pragma unroll
    for (int t = 0; t < 2; t++) {
        int d = lane + t * 32;
        float hp = hrow[d], lp = hrow[64 + d], hi = hrow[128 + d];
        float ah = arow[d], al = arow[64 + d];
        Hhp[t] = fmaxf(hp - (ah + inv * hp), 0.f);
        Hlp[t] = fmaxf(al + inv * lp, 0.f);
        Hi [t] = fmaxf(hi, 0.f);
        gh += Hhp[t] * wgh[d];
        gl += Hlp[t] * wgl[d];
        gi += Hi [t] * wgi[d];
    }
#pragma unroll
    for (int o = 16; o > 0; o >>= 1) {
        gh += __shfl_xor_sync(0xFFFFFFFFu, gh, o);
        gl += __shfl_xor_sync(0xFFFFFFFFu, gl, o);
        gi += __shfl_xor_sync(0xFFFFFFFFu, gi, o);
    }
    gh += bgh[0]; gl += bgl[0]; gi += bgi[0];

    float o0 = gh * Hhp[0] + gl * Hlp[0] + gi * Hi[0];
    float o1 = gh * Hhp[1] + gl * Hlp[1] + gi * Hi[1];

    float m = fmaxf(o0, o1);
#pragma unroll
    for (int o = 16; o > 0; o >>= 1) m = fmaxf(m, __shfl_xor_sync(0xFFFFFFFFu, m, o));
    float s = expf(o0 - m) + expf(o1 - m);
#pragma unroll
    for (int o = 16; o > 0; o >>= 1) s += __shfl_xor_sync(0xFFFFFFFFu, s, o);
    float lse = m + logf(s);

    out[(size_t)node * 64 + lane]      = o0 - lse;
    out[(size_t)node * 64 + lane + 32] = o1 - lse;
}

// ---------------- host launch ------------------------------------------------
extern "C" void kernel_launch(void* const* d_in, const int* in_sizes, int n_in,
                              void* d_out, int out_size) {
    const float* x  = (const float*)d_in[0];
    const void*  ei = d_in[1];
    const float* Whp = (const float*)d_in[2];
    const float* bhp = (const float*)d_in[3];
    const float* Wlp = (const float*)d_in[4];
    const float* blp = (const float*)d_in[5];
    const float* Wi  = (const float*)d_in[6];
    const float* bi  = (const float*)d_in[7];
    const float* wgh = (const float*)d_in[8];
    const float* bgh = (const float*)d_in[9];
    const float* wgl = (const float*)d_in[10];
    const float* bgl = (const float*)d_in[11];
    const float* wgi = (const float*)d_in[12];
    const float* bgi = (const float*)d_in[13];
    float* out = (float*)d_out;

    int n = in_sizes[0] / IN_DIM;   // 100000
    int E = in_sizes[1] / 2;        // 3200000
    int nb = (n + 1023) / 1024;     // scan blocks (<=128)

    static int smem_set = 0;
    if (!smem_set) {
        cudaFuncSetAttribute(k_gemm, cudaFuncAttributeMaxDynamicSharedMemorySize, GEMM_SMEM);
        smem_set = 1;
    }

    // k_gemm at launch index 3 so the fixed ncu capture slot lands on it.
    k_detect<<<1, 32>>>(ei, E, n);
    k_zero<<<(n + 255) / 256, 256>>>(n);
    k_prep_w<<<(IN_DIM * HCOLS + 255) / 256, 256>>>(Whp, bhp, Wlp, blp, Wi, bi);
    k_gemm<<<(n + 127) / 128, 512, GEMM_SMEM>>>(x, n);
    k_deg<<<(E + 255) / 256, 256>>>(ei, E, n);
    k_scan1<<<nb, 1024>>>(n);
    k_scan2<<<1, 128>>>(nb);
    k_scan3<<<(n + 255) / 256, 256>>>(n);
    k_scatter<<<(E + 255) / 256, 256>>>(ei, E, n);
    k_final<<<(n + 7) / 8, 256>>>(wgh, bgh, wgl, bgl, wgi, bgi, out, n);
}

// round 10
// speedup vs baseline: 1.9765x; 1.0825x over previous
#include <cuda_runtime.h>
#include <cuda_fp16.h>
#include <cstdint>

#define IN_DIM   256
#define OUT_DIM  64
#define HCOLS    192   // [hp | lp | i]
#define MAX_NODES 100000
#define MAX_EDGES 3300000

// ---------------- scratch (device globals: no allocations allowed) ----------
__device__ float   g_hall[(size_t)MAX_NODES * HCOLS];  // fp32 h (all paths)
__device__ __half2 g_hlp [(size_t)MAX_NODES * 64];     // fp16 mirror of cols 0..127 (gather)
__device__ int     g_deg [MAX_NODES];
__device__ int     g_cur [MAX_NODES];
__device__ int     g_rowp[MAX_NODES + 1];
__device__ int     g_adj [MAX_EDGES];
__device__ float   g_isq [MAX_NODES];
__device__ float   g_inv [MAX_NODES];
__device__ float   g_Wall[IN_DIM * HCOLS];             // pre-rounded to tf32 (rna)
__device__ float   g_ball[HCOLS];
__device__ int     g_is64;
__device__ int     g_bsum[128];

__device__ __forceinline__ uint32_t f2tf32(float f) {
    uint32_t u;
    asm("cvt.rna.tf32.f32 %0, %1;" : "=r"(u) : "f"(f));
    return u;
}

// ---------------- edge dtype detector (1 warp) -------------------------------
__global__ void k_detect(const void* __restrict__ ei, int E, int n) {
    const long long* p = (const long long*)ei;
    int lane = threadIdx.x;
    int idx = lane < E ? lane : (E > 0 ? E - 1 : 0);
    long long v = (E > 0) ? p[idx] : -1;
    bool good = (v >= 0 && v < (long long)n);
    unsigned all = __all_sync(0xFFFFFFFFu, good);
    if (lane == 0) g_is64 = all ? 1 : 0;
}

__device__ __forceinline__ int edge_at(const void* ei, size_t idx) {
    if (g_is64) return (int)((const long long*)ei)[idx];
    return ((const int*)ei)[idx];
}

// ---------------- zero deg + cursors -----------------------------------------
__global__ void k_zero(int n) {
    int i = blockIdx.x * blockDim.x + threadIdx.x;
    if (i < n) { g_deg[i] = 0; g_cur[i] = 0; }
}

// ---------------- pack weights (pre-rounded to tf32) -------------------------
__global__ void k_prep_w(const float* __restrict__ Whp, const float* __restrict__ bhp,
                         const float* __restrict__ Wlp, const float* __restrict__ blp,
                         const float* __restrict__ Wi,  const float* __restrict__ bi) {
    int idx = blockIdx.x * blockDim.x + threadIdx.x;
    if (idx < IN_DIM * HCOLS) {
        int k = idx / HCOLS, j = idx % HCOLS;
        float v;
        if      (j < 64)  v = Whp[k * 64 + j];
        else if (j < 128) v = Wlp[k * 64 + (j - 64)];
        else              v = Wi [k * 64 + (j - 128)];
        g_Wall[idx] = __uint_as_float(f2tf32(v));   // rna-rounded tf32 bits
    }
    if (idx < HCOLS) {
        g_ball[idx] = (idx < 64) ? bhp[idx] : (idx < 128 ? blp[idx - 64] : bi[idx - 128]);
    }
}

// ---------------- degree count -----------------------------------------------
__global__ void k_deg(const void* __restrict__ ei, int E, int n) {
    int e = blockIdx.x * blockDim.x + threadIdx.x;
    if (e < E) {
        int dst = edge_at(ei, (size_t)E + e);
        if ((unsigned)dst < (unsigned)n) atomicAdd(&g_deg[dst], 1);
    }
}

// ---------------- multi-block scan: deg -> row_ptr ---------------------------
__global__ void __launch_bounds__(1024) k_scan1(int n) {
    __shared__ int sh[1024];
    int i = blockIdx.x * 1024 + threadIdx.x;
    sh[threadIdx.x] = (i < n) ? g_deg[i] : 0;
    __syncthreads();
#pragma unroll
    for (int off = 1; off < 1024; off <<= 1) {
        int t = (threadIdx.x >= off) ? sh[threadIdx.x - off] : 0;
        __syncthreads();
        sh[threadIdx.x] += t;
        __syncthreads();
    }
    if (i < n) g_rowp[i + 1] = sh[threadIdx.x];
    if (threadIdx.x == 1023) g_bsum[blockIdx.x] = sh[1023];
}
__global__ void __launch_bounds__(128) k_scan2(int nb) {
    __shared__ int sh[128];
    sh[threadIdx.x] = (threadIdx.x < nb) ? g_bsum[threadIdx.x] : 0;
    __syncthreads();
#pragma unroll
    for (int off = 1; off < 128; off <<= 1) {
        int t = (threadIdx.x >= off) ? sh[threadIdx.x - off] : 0;
        __syncthreads();
        sh[threadIdx.x] += t;
        __syncthreads();
    }
    g_bsum[threadIdx.x] = sh[threadIdx.x];
}
// scan3 + degfin fused
__global__ void k_scan3(int n) {
    int i = blockIdx.x * blockDim.x + threadIdx.x;
    if (i < n) {
        int b = i >> 10;
        if (b > 0) g_rowp[i + 1] += g_bsum[b - 1];
        float d = (float)g_deg[i] + 1.0f;
        g_isq[i] = rsqrtf(d);
        g_inv[i] = 1.0f / d;
    }
    if (i == 0) g_rowp[0] = 0;
}

// ---------------- scatter edges into CSR -------------------------------------
__global__ void k_scatter(const void* __restrict__ ei, int E, int n) {
    int e = blockIdx.x * blockDim.x + threadIdx.x;
    if (e < E) {
        int src = edge_at(ei, (size_t)e);
        int dst = edge_at(ei, (size_t)E + e);
        if ((unsigned)src < (unsigned)n && (unsigned)dst < (unsigned)n) {
            int pos = g_rowp[dst] + atomicAdd(&g_cur[dst], 1);
            if ((unsigned)pos < (unsigned)MAX_EDGES) g_adj[pos] = src;
        }
    }
}

// ---------------- tf32 GEMM, cp.async double-buffered, NO per-fragment cvt ---
// BM=128, BN=192, BK=32; 512 thr = 16 warps (4x4); warp tile 32x48.
// A fragments pass raw fp32 bits (HW reads top tf32 bits = truncation);
// B was rna-rounded once in k_prep_w.
__device__ __forceinline__ void cp16(void* smem, const void* gmem) {
    uint32_t s = (uint32_t)__cvta_generic_to_shared(smem);
    asm volatile("cp.async.cg.shared.global [%0], [%1], 16;" :: "r"(s), "l"(gmem));
}

#define AS_STRIDE 36
#define BS_STRIDE 200
#define AS_ELEMS (128 * AS_STRIDE)       // 4608
#define BS_ELEMS (32 * BS_STRIDE)        // 6400
#define GEMM_SMEM ((2 * AS_ELEMS + 2 * BS_ELEMS) * 4)   // 88064 bytes

__global__ void __launch_bounds__(512) k_gemm(const float* __restrict__ x, int M) {
    extern __shared__ float smem[];
    float* As[2] = { smem, smem + AS_ELEMS };
    float* Bs[2] = { smem + 2 * AS_ELEMS, smem + 2 * AS_ELEMS + BS_ELEMS };

    const int tid  = threadIdx.x;
    const int wid  = tid >> 5;
    const int lane = tid & 31;
    const int m0 = blockIdx.x * 128;
    const int wm = (wid >> 2) * 32;
    const int wn = (wid & 3) * 48;
    const int grp = lane >> 2;
    const int tig = lane & 3;

    const int arow0 = tid >> 3,        acol = (tid & 7) * 4;
    const int brow[3] = { tid / 48, (tid + 512) / 48, (tid + 1024) / 48 };
    const int bcol[3] = { (tid % 48) * 4, ((tid + 512) % 48) * 4, ((tid + 1024) % 48) * 4 };

    auto load_stage = [&](int buf, int k0) {
#pragma unroll
        for (int r = 0; r < 2; r++) {
            int row = arow0 + r * 64;
            int m = m0 + row;
            int ms = m < M ? m : M - 1;
            cp16(&As[buf][row * AS_STRIDE + acol], x + (size_t)ms * IN_DIM + k0 + acol);
        }
#pragma unroll
        for (int r = 0; r < 3; r++) {
            cp16(&Bs[buf][brow[r] * BS_STRIDE + bcol[r]],
                 g_Wall + (size_t)(k0 + brow[r]) * HCOLS + bcol[r]);
        }
        asm volatile("cp.async.commit_group;");
    };

    float acc[2][6][4];
#pragma unroll
    for (int mi = 0; mi < 2; mi++)
#pragma unroll
        for (int ni = 0; ni < 6; ni++)
#pragma unroll
            for (int r = 0; r < 4; r++) acc[mi][ni][r] = 0.f;

    load_stage(0, 0);

    const int NIT = IN_DIM / 32;   // 8
    for (int it = 0; it < NIT; it++) {
        int buf = it & 1;
        if (it + 1 < NIT) {
            load_stage(buf ^ 1, (it + 1) * 32);
            asm volatile("cp.async.wait_group 1;");
        } else {
            asm volatile("cp.async.wait_group 0;");
        }
        __syncthreads();

        const float* A = As[buf];
        const float* B = Bs[buf];
#pragma unroll
        for (int kk = 0; kk < 4; kk++) {
            const int k8 = kk * 8;
            uint32_t ta[2][4], tb[6][2];
#pragma unroll
            for (int mi = 0; mi < 2; mi++) {
                int row = wm + mi * 16 + grp;
                ta[mi][0] = __float_as_uint(A[(row    ) * AS_STRIDE + k8 + tig    ]);
                ta[mi][1] = __float_as_uint(A[(row + 8) * AS_STRIDE + k8 + tig    ]);
                ta[mi][2] = __float_as_uint(A[(row    ) * AS_STRIDE + k8 + tig + 4]);
                ta[mi][3] = __float_as_uint(A[(row + 8) * AS_STRIDE + k8 + tig + 4]);
            }
#pragma unroll
            for (int ni = 0; ni < 6; ni++) {
                int col = wn + ni * 8 + grp;
                tb[ni][0] = __float_as_uint(B[(k8 + tig    ) * BS_STRIDE + col]);
                tb[ni][1] = __float_as_uint(B[(k8 + tig + 4) * BS_STRIDE + col]);
            }
#pragma unroll
            for (int mi = 0; mi < 2; mi++)
#pragma unroll
                for (int ni = 0; ni < 6; ni++) {
                    asm volatile(
                        "mma.sync.aligned.m16n8k8.row.col.f32.tf32.tf32.f32 "
                        "{%0,%1,%2,%3}, {%4,%5,%6,%7}, {%8,%9}, {%0,%1,%2,%3};"
                        : "+f"(acc[mi][ni][0]), "+f"(acc[mi][ni][1]),
                          "+f"(acc[mi][ni][2]), "+f"(acc[mi][ni][3])
                        : "r"(ta[mi][0]), "r"(ta[mi][1]), "r"(ta[mi][2]), "r"(ta[mi][3]),
                          "r"(tb[ni][0]), "r"(tb[ni][1]));
                }
        }
        __syncthreads();
    }

#pragma unroll
    for (int mi = 0; mi < 2; mi++) {
#pragma unroll
        for (int ni = 0; ni < 6; ni++) {
            int col = wn + ni * 8 + 2 * tig;
            float b0 = g_ball[col], b1 = g_ball[col + 1];
            int row = m0 + wm + mi * 16 + grp;
            if (row < M) {
                float2 o = make_float2(acc[mi][ni][0] + b0, acc[mi][ni][1] + b1);
                *reinterpret_cast<float2*>(g_hall + (size_t)row * HCOLS + col) = o;
                if (col < 128) g_hlp[(size_t)row * 64 + (col >> 1)] = __float22half2_rn(o);
            }
            if (row + 8 < M) {
                float2 o = make_float2(acc[mi][ni][2] + b0, acc[mi][ni][3] + b1);
                *reinterpret_cast<float2*>(g_hall + (size_t)(row + 8) * HCOLS + col) = o;
                if (col < 128) g_hlp[(size_t)(row + 8) * 64 + (col >> 1)] = __float22half2_rn(o);
            }
        }
    }
}

// ---------------- fused gather (fp16, unroll-4 MLP) + epilogue ---------------
__global__ void __launch_bounds__(256) k_final(
    const float* __restrict__ wgh, const float* __restrict__ bgh,
    const float* __restrict__ wgl, const float* __restrict__ bgl,
    const float* __restrict__ wgi, const float* __restrict__ bgi,
    float* __restrict__ out, int n)
{
    __shared__ float sagg[8][128];
    int wslot = threadIdx.x >> 5;
    int node = blockIdx.x * 8 + wslot;
    int lane = threadIdx.x & 31;
    if (node >= n) return;

    int beg = g_rowp[node], end = g_rowp[node + 1];
    float isqd = g_isq[node];

    float4 acc = make_float4(0.f, 0.f, 0.f, 0.f);
    int p = beg;
    for (; p + 4 <= end; p += 4) {
        int s0 = g_adj[p], s1 = g_adj[p + 1], s2 = g_adj[p + 2], s3 = g_adj[p + 3];
        float w0 = isqd * g_isq[s0], w1 = isqd * g_isq[s1];
        float w2 = isqd * g_isq[s2], w3 = isqd * g_isq[s3];
        uint2 r0 = *reinterpret_cast<const uint2*>(g_hlp + (size_t)s0 * 64 + 2 * lane);
        uint2 r1 = *reinterpret_cast<const uint2*>(g_hlp + (size_t)s1 * 64 + 2 * lane);
        uint2 r2 = *reinterpret_cast<const uint2*>(g_hlp + (size_t)s2 * 64 + 2 * lane);
        uint2 r3 = *reinterpret_cast<const uint2*>(g_hlp + (size_t)s3 * 64 + 2 * lane);
#define ACCUM(rr, ww) { \
        float2 f0 = __half22float2(*reinterpret_cast<__half2*>(&rr.x)); \
        float2 f1 = __half22float2(*reinterpret_cast<__half2*>(&rr.y)); \
        acc.x += ww * f0.x; acc.y += ww * f0.y; acc.z += ww * f1.x; acc.w += ww * f1.y; }
        ACCUM(r0, w0) ACCUM(r1, w1) ACCUM(r2, w2) ACCUM(r3, w3)
    }
    for (; p < end; p++) {
        int src = g_adj[p];
        float w = isqd * g_isq[src];
        uint2 raw = *reinterpret_cast<const uint2*>(g_hlp + (size_t)src * 64 + 2 * lane);
        ACCUM(raw, w)
    }
#undef ACCUM
    *reinterpret_cast<float4*>(&sagg[wslot][lane * 4]) = acc;
    __syncwarp();

    const float* hrow = g_hall + (size_t)node * HCOLS;
    const float* arow = sagg[wslot];
    float inv = g_inv[node];

    float Hhp[2], Hlp[2], Hi[2];
    float gh = 0.f, gl = 0.f, gi = 0.f;
#pragma unroll
    for (int t = 0; t < 2; t++) {
        int d = lane + t * 32;
        float hp = hrow[d], lp = hrow[64 + d], hi = hrow[128 + d];
        float ah = arow[d], al = arow[64 + d];
        Hhp[t] = fmaxf(hp - (ah + inv * hp), 0.f);
        Hlp[t] = fmaxf(al + inv * lp, 0.f);
        Hi [t] = fmaxf(hi, 0.f);
        gh += Hhp[t] * wgh[d];
        gl += Hlp[t] * wgl[d];
        gi += Hi [t] * wgi[d];
    }
#pragma unroll
    for (int o = 16; o > 0; o >>= 1) {
        gh += __shfl_xor_sync(0xFFFFFFFFu, gh, o);
        gl += __shfl_xor_sync(0xFFFFFFFFu, gl, o);
        gi += __shfl_xor_sync(0xFFFFFFFFu, gi, o);
    }
    gh += bgh[0]; gl += bgl[0]; gi += bgi[0];

    float o0 = gh * Hhp[0] + gl * Hlp[0] + gi * Hi[0];
    float o1 = gh * Hhp[1] + gl * Hlp[1] + gi * Hi[1];

    float m = fmaxf(o0, o1);
#pragma unroll
    for (int o = 16; o > 0; o >>= 1) m = fmaxf(m, __shfl_xor_sync(0xFFFFFFFFu, m, o));
    float s = expf(o0 - m) + expf(o1 - m);
#pragma unroll
    for (int o = 16; o > 0; o >>= 1) s += __shfl_xor_sync(0xFFFFFFFFu, s, o);
    float lse = m + logf(s);

    out[(size_t)node * 64 + lane]      = o0 - lse;
    out[(size_t)node * 64 + lane + 32] = o1 - lse;
}

// ---------------- host launch: fork prep chain onto a side stream ------------
extern "C" void kernel_launch(void* const* d_in, const int* in_sizes, int n_in,
                              void* d_out, int out_size) {
    const float* x  = (const float*)d_in[0];
    const void*  ei = d_in[1];
    const float* Whp = (const float*)d_in[2];
    const float* bhp = (const float*)d_in[3];
    const float* Wlp = (const float*)d_in[4];
    const float* blp = (const float*)d_in[5];
    const float* Wi  = (const float*)d_in[6];
    const float* bi  = (const float*)d_in[7];
    const float* wgh = (const float*)d_in[8];
    const float* bgh = (const float*)d_in[9];
    const float* wgl = (const float*)d_in[10];
    const float* bgl = (const float*)d_in[11];
    const float* wgi = (const float*)d_in[12];
    const float* bgi = (const float*)d_in[13];
    float* out = (float*)d_out;

    int n = in_sizes[0] / IN_DIM;   // 100000
    int E = in_sizes[1] / 2;        // 3200000
    int nb = (n + 1023) / 1024;

    static cudaStream_t s1 = nullptr;
    static cudaEvent_t ev_root = nullptr, ev_side = nullptr;
    if (!s1) {   // first call = uncaptured correctness call: safe to create
        cudaFuncSetAttribute(k_gemm, cudaFuncAttributeMaxDynamicSharedMemorySize, GEMM_SMEM);
        cudaStreamCreateWithFlags(&s1, cudaStreamNonBlocking);
        cudaEventCreateWithFlags(&ev_root, cudaEventDisableTiming);
        cudaEventCreateWithFlags(&ev_side, cudaEventDisableTiming);
    }

    // fork: side stream runs the CSR prep chain, main stream runs the GEMM.
    cudaEventRecord(ev_root, 0);
    cudaStreamWaitEvent(s1, ev_root, 0);

    k_detect<<<1, 32, 0, s1>>>(ei, E, n);
    k_zero<<<(n + 255) / 256, 256, 0, s1>>>(n);
    k_prep_w<<<(IN_DIM * HCOLS + 255) / 256, 256>>>(Whp, bhp, Wlp, blp, Wi, bi);
    k_gemm<<<(n + 127) / 128, 512, GEMM_SMEM>>>(x, n);   // launch idx 3 (profiled)
    k_deg<<<(E + 255) / 256, 256, 0, s1>>>(ei, E, n);
    k_scan1<<<nb, 1024, 0, s1>>>(n);
    k_scan2<<<1, 128, 0, s1>>>(nb);
    k_scan3<<<(n + 255) / 256, 256, 0, s1>>>(n);
    k_scatter<<<(E + 255) / 256, 256, 0, s1>>>(ei, E, n);

    // join: k_final needs both the GEMM output (stream 0) and CSR (s1).
    cudaEventRecord(ev_side, s1);
    cudaStreamWaitEvent(0, ev_side, 0);
    k_final<<<(n + 7) / 8, 256>>>(wgh, bgh, wgl, bgl, wgi, bgi, out, n);
}

// round 11
// speedup vs baseline: 2.1129x; 1.0690x over previous
#include <cuda_runtime.h>
#include <cuda_fp16.h>
#include <cstdint>

#define IN_DIM   256
#define OUT_DIM  64
#define HCOLS    192   // [hp | lp | i]
#define MAX_NODES 100000
#define MAX_EDGES 3300000

// ---------------- scratch (device globals: no allocations allowed) ----------
__device__ float   g_hall[(size_t)MAX_NODES * HCOLS];  // fp32 h (all paths)
__device__ __half2 g_hlp [(size_t)MAX_NODES * 64];     // fp16 mirror of cols 0..127; pre-scaled by isq[src]
__device__ int     g_deg [MAX_NODES];
__device__ int     g_cur [MAX_NODES];
__device__ int     g_rowp[MAX_NODES + 1];
__device__ int     g_adj [MAX_EDGES];
__device__ float   g_isq [MAX_NODES];
__device__ float   g_inv [MAX_NODES];
__device__ float   g_Wall[IN_DIM * HCOLS];             // pre-rounded to tf32 (rna)
__device__ float   g_ball[HCOLS];
__device__ int     g_is64;
__device__ int     g_bsum[128];

__device__ __forceinline__ uint32_t f2tf32(float f) {
    uint32_t u;
    asm("cvt.rna.tf32.f32 %0, %1;" : "=r"(u) : "f"(f));
    return u;
}

// ---------------- edge dtype detector (1 warp) -------------------------------
__global__ void k_detect(const void* __restrict__ ei, int E, int n) {
    const long long* p = (const long long*)ei;
    int lane = threadIdx.x;
    int idx = lane < E ? lane : (E > 0 ? E - 1 : 0);
    long long v = (E > 0) ? p[idx] : -1;
    bool good = (v >= 0 && v < (long long)n);
    unsigned all = __all_sync(0xFFFFFFFFu, good);
    if (lane == 0) g_is64 = all ? 1 : 0;
}

__device__ __forceinline__ int edge_at(const void* ei, size_t idx) {
    if (g_is64) return (int)((const long long*)ei)[idx];
    return ((const int*)ei)[idx];
}

// ---------------- zero deg + cursors -----------------------------------------
__global__ void k_zero(int n) {
    int i = blockIdx.x * blockDim.x + threadIdx.x;
    if (i < n) { g_deg[i] = 0; g_cur[i] = 0; }
}

// ---------------- pack weights (pre-rounded to tf32) -------------------------
__global__ void k_prep_w(const float* __restrict__ Whp, const float* __restrict__ bhp,
                         const float* __restrict__ Wlp, const float* __restrict__ blp,
                         const float* __restrict__ Wi,  const float* __restrict__ bi) {
    int idx = blockIdx.x * blockDim.x + threadIdx.x;
    if (idx < IN_DIM * HCOLS) {
        int k = idx / HCOLS, j = idx % HCOLS;
        float v;
        if      (j < 64)  v = Whp[k * 64 + j];
        else if (j < 128) v = Wlp[k * 64 + (j - 64)];
        else              v = Wi [k * 64 + (j - 128)];
        g_Wall[idx] = __uint_as_float(f2tf32(v));
    }
    if (idx < HCOLS) {
        g_ball[idx] = (idx < 64) ? bhp[idx] : (idx < 128 ? blp[idx - 64] : bi[idx - 128]);
    }
}

// ---------------- degree count -----------------------------------------------
__global__ void k_deg(const void* __restrict__ ei, int E, int n) {
    int e = blockIdx.x * blockDim.x + threadIdx.x;
    if (e < E) {
        int dst = edge_at(ei, (size_t)E + e);
        if ((unsigned)dst < (unsigned)n) atomicAdd(&g_deg[dst], 1);
    }
}

// ---------------- multi-block scan: deg -> row_ptr ---------------------------
__global__ void __launch_bounds__(1024) k_scan1(int n) {
    __shared__ int sh[1024];
    int i = blockIdx.x * 1024 + threadIdx.x;
    sh[threadIdx.x] = (i < n) ? g_deg[i] : 0;
    __syncthreads();
#pragma unroll
    for (int off = 1; off < 1024; off <<= 1) {
        int t = (threadIdx.x >= off) ? sh[threadIdx.x - off] : 0;
        __syncthreads();
        sh[threadIdx.x] += t;
        __syncthreads();
    }
    if (i < n) g_rowp[i + 1] = sh[threadIdx.x];
    if (threadIdx.x == 1023) g_bsum[blockIdx.x] = sh[1023];
}
__global__ void __launch_bounds__(128) k_scan2(int nb) {
    __shared__ int sh[128];
    sh[threadIdx.x] = (threadIdx.x < nb) ? g_bsum[threadIdx.x] : 0;
    __syncthreads();
#pragma unroll
    for (int off = 1; off < 128; off <<= 1) {
        int t = (threadIdx.x >= off) ? sh[threadIdx.x - off] : 0;
        __syncthreads();
        sh[threadIdx.x] += t;
        __syncthreads();
    }
    g_bsum[threadIdx.x] = sh[threadIdx.x];
}
// scan3 + degfin fused
__global__ void k_scan3(int n) {
    int i = blockIdx.x * blockDim.x + threadIdx.x;
    if (i < n) {
        int b = i >> 10;
        if (b > 0) g_rowp[i + 1] += g_bsum[b - 1];
        float d = (float)g_deg[i] + 1.0f;
        g_isq[i] = rsqrtf(d);
        g_inv[i] = 1.0f / d;
    }
    if (i == 0) g_rowp[0] = 0;
}

// ---------------- scatter edges into CSR -------------------------------------
__global__ void k_scatter(const void* __restrict__ ei, int E, int n) {
    int e = blockIdx.x * blockDim.x + threadIdx.x;
    if (e < E) {
        int src = edge_at(ei, (size_t)e);
        int dst = edge_at(ei, (size_t)E + e);
        if ((unsigned)src < (unsigned)n && (unsigned)dst < (unsigned)n) {
            int pos = g_rowp[dst] + atomicAdd(&g_cur[dst], 1);
            if ((unsigned)pos < (unsigned)MAX_EDGES) g_adj[pos] = src;
        }
    }
}

// ---------------- prescale: g_hlp[i] *= isq[i] (row-wise) --------------------
// Safe under graph replay: k_gemm rewrites g_hlp before this every launch.
__global__ void k_prescale(int n) {
    int t = blockIdx.x * blockDim.x + threadIdx.x;   // one uint2 (2 half2) per thread
    int total = n * 32;                               // 64 half2 per node / 2
    if (t >= total) return;
    int node = t >> 5;
    float s = g_isq[node];
    uint2 raw = *reinterpret_cast<const uint2*>(g_hlp + (size_t)t * 2);
    float2 f0 = __half22float2(*reinterpret_cast<__half2*>(&raw.x));
    float2 f1 = __half22float2(*reinterpret_cast<__half2*>(&raw.y));
    f0.x *= s; f0.y *= s; f1.x *= s; f1.y *= s;
    __half2 h0 = __float22half2_rn(f0), h1 = __float22half2_rn(f1);
    uint2 o; o.x = *reinterpret_cast<uint32_t*>(&h0); o.y = *reinterpret_cast<uint32_t*>(&h1);
    *reinterpret_cast<uint2*>(g_hlp + (size_t)t * 2) = o;
}

// ---------------- tf32 GEMM, cp.async double-buffered ------------------------
__device__ __forceinline__ void cp16(void* smem, const void* gmem) {
    uint32_t s = (uint32_t)__cvta_generic_to_shared(smem);
    asm volatile("cp.async.cg.shared.global [%0], [%1], 16;" :: "r"(s), "l"(gmem));
}

#define AS_STRIDE 36
#define BS_STRIDE 200
#define AS_ELEMS (128 * AS_STRIDE)
#define BS_ELEMS (32 * BS_STRIDE)
#define GEMM_SMEM ((2 * AS_ELEMS + 2 * BS_ELEMS) * 4)   // 88064 bytes

__global__ void __launch_bounds__(512) k_gemm(const float* __restrict__ x, int M) {
    extern __shared__ float smem[];
    float* As[2] = { smem, smem + AS_ELEMS };
    float* Bs[2] = { smem + 2 * AS_ELEMS, smem + 2 * AS_ELEMS + BS_ELEMS };

    const int tid  = threadIdx.x;
    const int wid  = tid >> 5;
    const int lane = tid & 31;
    const int m0 = blockIdx.x * 128;
    const int wm = (wid >> 2) * 32;
    const int wn = (wid & 3) * 48;
    const int grp = lane >> 2;
    const int tig = lane & 3;

    const int arow0 = tid >> 3,        acol = (tid & 7) * 4;
    const int brow[3] = { tid / 48, (tid + 512) / 48, (tid + 1024) / 48 };
    const int bcol[3] = { (tid % 48) * 4, ((tid + 512) % 48) * 4, ((tid + 1024) % 48) * 4 };

    auto load_stage = [&](int buf, int k0) {
#pragma unroll
        for (int r = 0; r < 2; r++) {
            int row = arow0 + r * 64;
            int m = m0 + row;
            int ms = m < M ? m : M - 1;
            cp16(&As[buf][row * AS_STRIDE + acol], x + (size_t)ms * IN_DIM + k0 + acol);
        }
#pragma unroll
        for (int r = 0; r < 3; r++) {
            cp16(&Bs[buf][brow[r] * BS_STRIDE + bcol[r]],
                 g_Wall + (size_t)(k0 + brow[r]) * HCOLS + bcol[r]);
        }
        asm volatile("cp.async.commit_group;");
    };

    float acc[2][6][4];
#pragma unroll
    for (int mi = 0; mi < 2; mi++)
#pragma unroll
        for (int ni = 0; ni < 6; ni++)
#pragma unroll
            for (int r = 0; r < 4; r++) acc[mi][ni][r] = 0.f;

    load_stage(0, 0);

    const int NIT = IN_DIM / 32;
    for (int it = 0; it < NIT; it++) {
        int buf = it & 1;
        if (it + 1 < NIT) {
            load_stage(buf ^ 1, (it + 1) * 32);
            asm volatile("cp.async.wait_group 1;");
        } else {
            asm volatile("cp.async.wait_group 0;");
        }
        __syncthreads();

        const float* A = As[buf];
        const float* B = Bs[buf];
#pragma unroll
        for (int kk = 0; kk < 4; kk++) {
            const int k8 = kk * 8;
            uint32_t ta[2][4], tb[6][2];
#pragma unroll
            for (int mi = 0; mi < 2; mi++) {
                int row = wm + mi * 16 + grp;
                ta[mi][0] = __float_as_uint(A[(row    ) * AS_STRIDE + k8 + tig    ]);
                ta[mi][1] = __float_as_uint(A[(row + 8) * AS_STRIDE + k8 + tig    ]);
                ta[mi][2] = __float_as_uint(A[(row    ) * AS_STRIDE + k8 + tig + 4]);
                ta[mi][3] = __float_as_uint(A[(row + 8) * AS_STRIDE + k8 + tig + 4]);
            }
#pragma unroll
            for (int ni = 0; ni < 6; ni++) {
                int col = wn + ni * 8 + grp;
                tb[ni][0] = __float_as_uint(B[(k8 + tig    ) * BS_STRIDE + col]);
                tb[ni][1] = __float_as_uint(B[(k8 + tig + 4) * BS_STRIDE + col]);
            }
#pragma unroll
            for (int mi = 0; mi < 2; mi++)
#pragma unroll
                for (int ni = 0; ni < 6; ni++) {
                    asm volatile(
                        "mma.sync.aligned.m16n8k8.row.col.f32.tf32.tf32.f32 "
                        "{%0,%1,%2,%3}, {%4,%5,%6,%7}, {%8,%9}, {%0,%1,%2,%3};"
                        : "+f"(acc[mi][ni][0]), "+f"(acc[mi][ni][1]),
                          "+f"(acc[mi][ni][2]), "+f"(acc[mi][ni][3])
                        : "r"(ta[mi][0]), "r"(ta[mi][1]), "r"(ta[mi][2]), "r"(ta[mi][3]),
                          "r"(tb[ni][0]), "r"(tb[ni][1]));
                }
        }
        __syncthreads();
    }

#pragma unroll
    for (int mi = 0; mi < 2; mi++) {
#pragma unroll
        for (int ni = 0; ni < 6; ni++) {
            int col = wn + ni * 8 + 2 * tig;
            float b0 = g_ball[col], b1 = g_ball[col + 1];
            int row = m0 + wm + mi * 16 + grp;
            if (row < M) {
                float2 o = make_float2(acc[mi][ni][0] + b0, acc[mi][ni][1] + b1);
                *reinterpret_cast<float2*>(g_hall + (size_t)row * HCOLS + col) = o;
                if (col < 128) g_hlp[(size_t)row * 64 + (col >> 1)] = __float22half2_rn(o);
            }
            if (row + 8 < M) {
                float2 o = make_float2(acc[mi][ni][2] + b0, acc[mi][ni][3] + b1);
                *reinterpret_cast<float2*>(g_hall + (size_t)(row + 8) * HCOLS + col) = o;
                if (col < 128) g_hlp[(size_t)(row + 8) * 64 + (col >> 1)] = __float22half2_rn(o);
            }
        }
    }
}

// ---------------- fused gather (pre-scaled rows, unroll-8) + epilogue --------
__global__ void __launch_bounds__(256) k_final(
    const float* __restrict__ wgh, const float* __restrict__ bgh,
    const float* __restrict__ wgl, const float* __restrict__ bgl,
    const float* __restrict__ wgi, const float* __restrict__ bgi,
    float* __restrict__ out, int n)
{
    __shared__ float sagg[8][128];
    int wslot = threadIdx.x >> 5;
    int node = blockIdx.x * 8 + wslot;
    int lane = threadIdx.x & 31;
    if (node >= n) return;

    int beg = g_rowp[node], end = g_rowp[node + 1];
    float isqd = g_isq[node];

    // rows are pre-scaled by isq[src]; agg = isq_dst * sum(rows)
    float4 acc = make_float4(0.f, 0.f, 0.f, 0.f);
#define ROWLD(ss) *reinterpret_cast<const uint2*>(g_hlp + (size_t)(ss) * 64 + 2 * lane)
#define ACCUM(rr) { \
        float2 f0 = __half22float2(*reinterpret_cast<__half2*>(&rr.x)); \
        float2 f1 = __half22float2(*reinterpret_cast<__half2*>(&rr.y)); \
        acc.x += f0.x; acc.y += f0.y; acc.z += f1.x; acc.w += f1.y; }
    int p = beg;
    for (; p + 8 <= end; p += 8) {
        int s0 = g_adj[p],     s1 = g_adj[p + 1], s2 = g_adj[p + 2], s3 = g_adj[p + 3];
        int s4 = g_adj[p + 4], s5 = g_adj[p + 5], s6 = g_adj[p + 6], s7 = g_adj[p + 7];
        uint2 r0 = ROWLD(s0), r1 = ROWLD(s1), r2 = ROWLD(s2), r3 = ROWLD(s3);
        uint2 r4 = ROWLD(s4), r5 = ROWLD(s5), r6 = ROWLD(s6), r7 = ROWLD(s7);
        ACCUM(r0) ACCUM(r1) ACCUM(r2) ACCUM(r3)
        ACCUM(r4) ACCUM(r5) ACCUM(r6) ACCUM(r7)
    }
    for (; p < end; p++) {
        int src = g_adj[p];
        uint2 raw = ROWLD(src);
        ACCUM(raw)
    }
#undef ACCUM
#undef ROWLD
    acc.x *= isqd; acc.y *= isqd; acc.z *= isqd; acc.w *= isqd;
    *reinterpret_cast<float4*>(&sagg[wslot][lane * 4]) = acc;
    __syncwarp();

    const float* hrow = g_hall + (size_t)node * HCOLS;
    const float* arow = sagg[wslot];
    float inv = g_inv[node];

    float Hhp[2], Hlp[2], Hi[2];
    float gh = 0.f, gl = 0.f, gi = 0.f;
#pragma unroll
    for (int t = 0; t < 2; t++) {
        int d = lane + t * 32;
        float hp = hrow[d], lp = hrow[64 + d], hi = hrow[128 + d];
        float ah = arow[d], al = arow[64 + d];
        Hhp[t] = fmaxf(hp - (ah + inv * hp), 0.f);
        Hlp[t] = fmaxf(al + inv * lp, 0.f);
        Hi [t] = fmaxf(hi, 0.f);
        gh += Hhp[t] * wgh[d];
        gl += Hlp[t] * wgl[d];
        gi += Hi [t] * wgi[d];
    }
#pragma unroll
    for (int o = 16; o > 0; o >>= 1) {
        gh += __shfl_xor_sync(0xFFFFFFFFu, gh, o);
        gl += __shfl_xor_sync(0xFFFFFFFFu, gl, o);
        gi += __shfl_xor_sync(0xFFFFFFFFu, gi, o);
    }
    gh += bgh[0]; gl += bgl[0]; gi += bgi[0];

    float o0 = gh * Hhp[0] + gl * Hlp[0] + gi * Hi[0];
    float o1 = gh * Hhp[1] + gl * Hlp[1] + gi * Hi[1];

    float m = fmaxf(o0, o1);
#pragma unroll
    for (int o = 16; o > 0; o >>= 1) m = fmaxf(m, __shfl_xor_sync(0xFFFFFFFFu, m, o));
    float s = expf(o0 - m) + expf(o1 - m);
#pragma unroll
    for (int o = 16; o > 0; o >>= 1) s += __shfl_xor_sync(0xFFFFFFFFu, s, o);
    float lse = m + logf(s);

    out[(size_t)node * 64 + lane]      = o0 - lse;
    out[(size_t)node * 64 + lane + 32] = o1 - lse;
}

// ---------------- host launch ------------------------------------------------
extern "C" void kernel_launch(void* const* d_in, const int* in_sizes, int n_in,
                              void* d_out, int out_size) {
    const float* x  = (const float*)d_in[0];
    const void*  ei = d_in[1];
    const float* Whp = (const float*)d_in[2];
    const float* bhp = (const float*)d_in[3];
    const float* Wlp = (const float*)d_in[4];
    const float* blp = (const float*)d_in[5];
    const float* Wi  = (const float*)d_in[6];
    const float* bi  = (const float*)d_in[7];
    const float* wgh = (const float*)d_in[8];
    const float* bgh = (const float*)d_in[9];
    const float* wgl = (const float*)d_in[10];
    const float* bgl = (const float*)d_in[11];
    const float* wgi = (const float*)d_in[12];
    const float* bgi = (const float*)d_in[13];
    float* out = (float*)d_out;

    int n = in_sizes[0] / IN_DIM;   // 100000
    int E = in_sizes[1] / 2;        // 3200000
    int nb = (n + 1023) / 1024;

    static cudaStream_t s1 = nullptr;
    static cudaEvent_t ev_root = nullptr, ev_isq = nullptr, ev_side = nullptr;
    if (!s1) {   // first call = uncaptured correctness call: safe to create
        cudaFuncSetAttribute(k_gemm, cudaFuncAttributeMaxDynamicSharedMemorySize, GEMM_SMEM);
        cudaStreamCreateWithFlags(&s1, cudaStreamNonBlocking);
        cudaEventCreateWithFlags(&ev_root, cudaEventDisableTiming);
        cudaEventCreateWithFlags(&ev_isq,  cudaEventDisableTiming);
        cudaEventCreateWithFlags(&ev_side, cudaEventDisableTiming);
    }

    cudaEventRecord(ev_root, 0);
    cudaStreamWaitEvent(s1, ev_root, 0);

    k_detect<<<1, 32, 0, s1>>>(ei, E, n);
    k_zero<<<(n + 255) / 256, 256, 0, s1>>>(n);
    k_prep_w<<<(IN_DIM * HCOLS + 255) / 256, 256>>>(Whp, bhp, Wlp, blp, Wi, bi);
    k_gemm<<<(n + 127) / 128, 512, GEMM_SMEM>>>(x, n);   // launch idx 3 (profiled)
    k_deg<<<(E + 255) / 256, 256, 0, s1>>>(ei, E, n);
    k_scan1<<<nb, 1024, 0, s1>>>(n);
    k_scan2<<<1, 128, 0, s1>>>(nb);
    k_scan3<<<(n + 255) / 256, 256, 0, s1>>>(n);
    cudaEventRecord(ev_isq, s1);                          // isq/inv ready
    k_scatter<<<(E + 255) / 256, 256, 0, s1>>>(ei, E, n);
    cudaEventRecord(ev_side, s1);                         // CSR ready

    // prescale needs gemm output (stream 0) + isq (s1); overlaps with scatter
    cudaStreamWaitEvent(0, ev_isq, 0);
    k_prescale<<<(n * 32 + 255) / 256, 256>>>(n);

    cudaStreamWaitEvent(0, ev_side, 0);
    k_final<<<(n + 7) / 8, 256>>>(wgh, bgh, wgl, bgl, wgi, bgi, out, n);
}

// round 13
// speedup vs baseline: 2.1588x; 1.0217x over previous
#include <cuda_runtime.h>
#include <cuda_fp16.h>
#include <cstdint>

#define IN_DIM   256
#define OUT_DIM  64
#define HCOLS    192   // [hp | lp | i]
#define MAX_NODES 100000
#define MAX_EDGES 3300000

// ---------------- scratch (device globals: no allocations allowed) ----------
__device__ float   g_hall[(size_t)MAX_NODES * HCOLS];  // fp32 h (all paths)
__device__ __half2 g_hlp [(size_t)MAX_NODES * 64];     // fp16 mirror of cols 0..127; pre-scaled by isq[src]
__device__ __half  g_xh  [(size_t)MAX_NODES * IN_DIM]; // fp16 mirror of x
__device__ __half  g_Wth [HCOLS * IN_DIM];             // fp16 W, TRANSPOSED: [n][k]
__device__ int     g_deg [MAX_NODES];
__device__ int     g_cur [MAX_NODES];
__device__ int     g_rowp[MAX_NODES + 1];
__device__ int     g_adj [MAX_EDGES];
__device__ float   g_isq [MAX_NODES];
__device__ float   g_inv [MAX_NODES];
__device__ float   g_ball[HCOLS];
__device__ int     g_is64;
__device__ int     g_bsum[128];

// ---------------- edge dtype detector (1 warp) -------------------------------
__global__ void k_detect(const void* __restrict__ ei, int E, int n) {
    const long long* p = (const long long*)ei;
    int lane = threadIdx.x;
    int idx = lane < E ? lane : (E > 0 ? E - 1 : 0);
    long long v = (E > 0) ? p[idx] : -1;
    bool good = (v >= 0 && v < (long long)n);
    unsigned all = __all_sync(0xFFFFFFFFu, good);
    if (lane == 0) g_is64 = all ? 1 : 0;
}

__device__ __forceinline__ int edge_at(const void* ei, size_t idx) {
    if (g_is64) return (int)((const long long*)ei)[idx];
    return ((const int*)ei)[idx];
}

// ---------------- x -> fp16 mirror -------------------------------------------
__global__ void k_xh(const float* __restrict__ x, int total4) {
    int t = blockIdx.x * blockDim.x + threadIdx.x;   // one float4 -> one uint2 (4 halves)
    if (t >= total4) return;
    float4 v = reinterpret_cast<const float4*>(x)[t];
    __half2 h0 = __float22half2_rn(make_float2(v.x, v.y));
    __half2 h1 = __float22half2_rn(make_float2(v.z, v.w));
    uint2 o;
    o.x = *reinterpret_cast<uint32_t*>(&h0);
    o.y = *reinterpret_cast<uint32_t*>(&h1);
    reinterpret_cast<uint2*>(g_xh)[t] = o;
}

// ---------------- zero deg + cursors -----------------------------------------
__global__ void k_zero(int n) {
    int i = blockIdx.x * blockDim.x + threadIdx.x;
    if (i < n) { g_deg[i] = 0; g_cur[i] = 0; }
}

// ---------------- pack weights: fp16, transposed to [n][k] -------------------
__global__ void k_prep_w(const float* __restrict__ Whp, const float* __restrict__ bhp,
                         const float* __restrict__ Wlp, const float* __restrict__ blp,
                         const float* __restrict__ Wi,  const float* __restrict__ bi) {
    int idx = blockIdx.x * blockDim.x + threadIdx.x;
    if (idx < IN_DIM * HCOLS) {
        int k = idx / HCOLS, j = idx % HCOLS;
        float v;
        if      (j < 64)  v = Whp[k * 64 + j];
        else if (j < 128) v = Wlp[k * 64 + (j - 64)];
        else              v = Wi [k * 64 + (j - 128)];
        g_Wth[(size_t)j * IN_DIM + k] = __float2half_rn(v);
    }
    if (idx < HCOLS) {
        g_ball[idx] = (idx < 64) ? bhp[idx] : (idx < 128 ? blp[idx - 64] : bi[idx - 128]);
    }
}

// ---------------- degree count -----------------------------------------------
__global__ void k_deg(const void* __restrict__ ei, int E, int n) {
    int e = blockIdx.x * blockDim.x + threadIdx.x;
    if (e < E) {
        int dst = edge_at(ei, (size_t)E + e);
        if ((unsigned)dst < (unsigned)n) atomicAdd(&g_deg[dst], 1);
    }
}

// ---------------- multi-block scan: deg -> row_ptr ---------------------------
__global__ void __launch_bounds__(1024) k_scan1(int n) {
    __shared__ int sh[1024];
    int i = blockIdx.x * 1024 + threadIdx.x;
    sh[threadIdx.x] = (i < n) ? g_deg[i] : 0;
    __syncthreads();
#pragma unroll
    for (int off = 1; off < 1024; off <<= 1) {
        int t = (threadIdx.x >= off) ? sh[threadIdx.x - off] : 0;
        __syncthreads();
        sh[threadIdx.x] += t;
        __syncthreads();
    }
    if (i < n) g_rowp[i + 1] = sh[threadIdx.x];
    if (threadIdx.x == 1023) g_bsum[blockIdx.x] = sh[1023];
}
__global__ void __launch_bounds__(128) k_scan2(int nb) {
    __shared__ int sh[128];
    sh[threadIdx.x] = (threadIdx.x < nb) ? g_bsum[threadIdx.x] : 0;
    __syncthreads();
#pragma unroll
    for (int off = 1; off < 128; off <<= 1) {
        int t = (threadIdx.x >= off) ? sh[threadIdx.x - off] : 0;
        __syncthreads();
        sh[threadIdx.x] += t;
        __syncthreads();
    }
    g_bsum[threadIdx.x] = sh[threadIdx.x];
}
// scan3 + degfin fused
__global__ void k_scan3(int n) {
    int i = blockIdx.x * blockDim.x + threadIdx.x;
    if (i < n) {
        int b = i >> 10;
        if (b > 0) g_rowp[i + 1] += g_bsum[b - 1];
        float d = (float)g_deg[i] + 1.0f;
        g_isq[i] = rsqrtf(d);
        g_inv[i] = 1.0f / d;
    }
    if (i == 0) g_rowp[0] = 0;
}

// ---------------- scatter edges into CSR -------------------------------------
__global__ void k_scatter(const void* __restrict__ ei, int E, int n) {
    int e = blockIdx.x * blockDim.x + threadIdx.x;
    if (e < E) {
        int src = edge_at(ei, (size_t)e);
        int dst = edge_at(ei, (size_t)E + e);
        if ((unsigned)src < (unsigned)n && (unsigned)dst < (unsigned)n) {
            int pos = g_rowp[dst] + atomicAdd(&g_cur[dst], 1);
            if ((unsigned)pos < (unsigned)MAX_EDGES) g_adj[pos] = src;
        }
    }
}

// ---------------- prescale: g_hlp[i] *= isq[i] (row-wise) --------------------
// Safe under graph replay: k_gemm rewrites g_hlp before this every launch.
__global__ void k_prescale(int n) {
    int t = blockIdx.x * blockDim.x + threadIdx.x;
    int total = n * 32;
    if (t >= total) return;
    int node = t >> 5;
    float s = g_isq[node];
    uint2 raw = *reinterpret_cast<const uint2*>(g_hlp + (size_t)t * 2);
    float2 f0 = __half22float2(*reinterpret_cast<__half2*>(&raw.x));
    float2 f1 = __half22float2(*reinterpret_cast<__half2*>(&raw.y));
    f0.x *= s; f0.y *= s; f1.x *= s; f1.y *= s;
    __half2 h0 = __float22half2_rn(f0), h1 = __float22half2_rn(f1);
    uint2 o; o.x = *reinterpret_cast<uint32_t*>(&h0); o.y = *reinterpret_cast<uint32_t*>(&h1);
    *reinterpret_cast<uint2*>(g_hlp + (size_t)t * 2) = o;
}

// ---------------- fp16 GEMM, cp.async double-buffered ------------------------
// BM=128, BN=192, BK=32; 512 thr = 16 warps (4x4); warp tile 32x48.
// mma.sync.m16n8k16.f32.f16.f16.f32; A from g_xh [m][k], B from g_Wth [n][k].
__device__ __forceinline__ void cp16(void* smem, const void* gmem) {
    uint32_t s = (uint32_t)__cvta_generic_to_shared(smem);
    asm volatile("cp.async.cg.shared.global [%0], [%1], 16;" :: "r"(s), "l"(gmem));
}

#define AS_STRIDE 40                       // halves per row (32 + 8 pad); 80 B, 16B-aligned
#define AS_ELEMS (128 * AS_STRIDE)         // per buffer
#define BS_ELEMS (HCOLS * AS_STRIDE)
#define GEMM_SMEM ((2 * AS_ELEMS + 2 * BS_ELEMS) * 2)   // 51200 bytes

__global__ void __launch_bounds__(512) k_gemm(int M) {
    extern __shared__ __half hsmem[];
    __half* As[2] = { hsmem, hsmem + AS_ELEMS };
    __half* Bs[2] = { hsmem + 2 * AS_ELEMS, hsmem + 2 * AS_ELEMS + BS_ELEMS };

    const int tid  = threadIdx.x;
    const int wid  = tid >> 5;
    const int lane = tid & 31;
    const int m0 = blockIdx.x * 128;
    const int wm = (wid >> 2) * 32;
    const int wn = (wid & 3) * 48;
    const int grp = lane >> 2;          // 0..7
    const int tig = lane & 3;           // 0..3

    // A stage: 128 rows x 4 chunks(16B) = 512 -> 1/thread
    const int arow = tid >> 2, achk = (tid & 3) * 8;       // halves offset
    // B stage: 192 rows x 4 chunks = 768 -> 1.5/thread
    auto load_stage = [&](int buf, int k0) {
        {
            int m = m0 + arow;
            int ms = m < M ? m : M - 1;
            cp16(&As[buf][arow * AS_STRIDE + achk], g_xh + (size_t)ms * IN_DIM + k0 + achk);
        }
#pragma unroll
        for (int r = 0; r < 2; r++) {
            int f = tid + r * 512;
            if (f < HCOLS * 4) {
                int row = f >> 2, chk = (f & 3) * 8;
                cp16(&Bs[buf][row * AS_STRIDE + chk], g_Wth + (size_t)row * IN_DIM + k0 + chk);
            }
        }
        asm volatile("cp.async.commit_group;");
    };

    float acc[2][6][4];
#pragma unroll
    for (int mi = 0; mi < 2; mi++)
#pragma unroll
        for (int ni = 0; ni < 6; ni++)
#pragma unroll
            for (int r = 0; r < 4; r++) acc[mi][ni][r] = 0.f;

    load_stage(0, 0);

    const int NIT = IN_DIM / 32;   // 8
    for (int it = 0; it < NIT; it++) {
        int buf = it & 1;
        if (it + 1 < NIT) {
            load_stage(buf ^ 1, (it + 1) * 32);
            asm volatile("cp.async.wait_group 1;");
        } else {
            asm volatile("cp.async.wait_group 0;");
        }
        __syncthreads();

        const __half* A = As[buf];
        const __half* B = Bs[buf];
#pragma unroll
        for (int ks = 0; ks < 2; ks++) {
            const int k16 = ks * 16;
            uint32_t ta[2][4], tb[6][2];
#pragma unroll
            for (int mi = 0; mi < 2; mi++) {
                int row = wm + mi * 16 + grp;
                ta[mi][0] = *reinterpret_cast<const uint32_t*>(&A[(row    ) * AS_STRIDE + k16 + 2 * tig    ]);
                ta[mi][1] = *reinterpret_cast<const uint32_t*>(&A[(row + 8) * AS_STRIDE + k16 + 2 * tig    ]);
                ta[mi][2] = *reinterpret_cast<const uint32_t*>(&A[(row    ) * AS_STRIDE + k16 + 2 * tig + 8]);
                ta[mi][3] = *reinterpret_cast<const uint32_t*>(&A[(row + 8) * AS_STRIDE + k16 + 2 * tig + 8]);
            }
#pragma unroll
            for (int ni = 0; ni < 6; ni++) {
                int col = wn + ni * 8 + grp;
                tb[ni][0] = *reinterpret_cast<const uint32_t*>(&B[col * AS_STRIDE + k16 + 2 * tig    ]);
                tb[ni][1] = *reinterpret_cast<const uint32_t*>(&B[col * AS_STRIDE + k16 + 2 * tig + 8]);
            }
#pragma unroll
            for (int mi = 0; mi < 2; mi++)
#pragma unroll
                for (int ni = 0; ni < 6; ni++) {
                    asm volatile(
                        "mma.sync.aligned.m16n8k16.row.col.f32.f16.f16.f32 "
                        "{%0,%1,%2,%3}, {%4,%5,%6,%7}, {%8,%9}, {%0,%1,%2,%3};"
                        : "+f"(acc[mi][ni][0]), "+f"(acc[mi][ni][1]),
                          "+f"(acc[mi][ni][2]), "+f"(acc[mi][ni][3])
                        : "r"(ta[mi][0]), "r"(ta[mi][1]), "r"(ta[mi][2]), "r"(ta[mi][3]),
                          "r"(tb[ni][0]), "r"(tb[ni][1]));
                }
        }
        __syncthreads();
    }

#pragma unroll
    for (int mi = 0; mi < 2; mi++) {
#pragma unroll
        for (int ni = 0; ni < 6; ni++) {
            int col = wn + ni * 8 + 2 * tig;
            float b0 = g_ball[col], b1 = g_ball[col + 1];
            int row = m0 + wm + mi * 16 + grp;
            if (row < M) {
                float2 o = make_float2(acc[mi][ni][0] + b0, acc[mi][ni][1] + b1);
                *reinterpret_cast<float2*>(g_hall + (size_t)row * HCOLS + col) = o;
                if (col < 128) g_hlp[(size_t)row * 64 + (col >> 1)] = __float22half2_rn(o);
            }
            if (row + 8 < M) {
                float2 o = make_float2(acc[mi][ni][2] + b0, acc[mi][ni][3] + b1);
                *reinterpret_cast<float2*>(g_hall + (size_t)(row + 8) * HCOLS + col) = o;
                if (col < 128) g_hlp[(size_t)(row + 8) * 64 + (col >> 1)] = __float22half2_rn(o);
            }
        }
    }
}

// ---------------- fused gather (pre-scaled rows, unroll-8) + epilogue --------
__global__ void __launch_bounds__(256) k_final(
    const float* __restrict__ wgh, const float* __restrict__ bgh,
    const float* __restrict__ wgl, const float* __restrict__ bgl,
    const float* __restrict__ wgi, const float* __restrict__ bgi,
    float* __restrict__ out, int n)
{
    __shared__ float sagg[8][128];
    int wslot = threadIdx.x >> 5;
    int node = blockIdx.x * 8 + wslot;
    int lane = threadIdx.x & 31;
    if (node >= n) return;

    int beg = g_rowp[node], end = g_rowp[node + 1];
    float isqd = g_isq[node];

    float4 acc = make_float4(0.f, 0.f, 0.f, 0.f);
#define ROWLD(ss) *reinterpret_cast<const uint2*>(g_hlp + (size_t)(ss) * 64 + 2 * lane)
#define ACCUM(rr) { \
        float2 f0 = __half22float2(*reinterpret_cast<__half2*>(&rr.x)); \
        float2 f1 = __half22float2(*reinterpret_cast<__half2*>(&rr.y)); \
        acc.x += f0.x; acc.y += f0.y; acc.z += f1.x; acc.w += f1.y; }
    int p = beg;
    for (; p + 8 <= end; p += 8) {
        int s0 = g_adj[p],     s1 = g_adj[p + 1], s2 = g_adj[p + 2], s3 = g_adj[p + 3];
        int s4 = g_adj[p + 4], s5 = g_adj[p + 5], s6 = g_adj[p + 6], s7 = g_adj[p + 7];
        uint2 r0 = ROWLD(s0), r1 = ROWLD(s1), r2 = ROWLD(s2), r3 = ROWLD(s3);
        uint2 r4 = ROWLD(s4), r5 = ROWLD(s5), r6 = ROWLD(s6), r7 = ROWLD(s7);
        ACCUM(r0) ACCUM(r1) ACCUM(r2) ACCUM(r3)
        ACCUM(r4) ACCUM(r5) ACCUM(r6) ACCUM(r7)
    }
    for (; p < end; p++) {
        int src = g_adj[p];
        uint2 raw = ROWLD(src);
        ACCUM(raw)
    }
#undef ACCUM
#undef ROWLD
    acc.x *= isqd; acc.y *= isqd; acc.z *= isqd; acc.w *= isqd;
    *reinterpret_cast<float4*>(&sagg[wslot][lane * 4]) = acc;
    __syncwarp();

    const float* hrow = g_hall + (size_t)node * HCOLS;
    const float* arow = sagg[wslot];
    float inv = g_inv[node];

    float Hhp[2], Hlp[2], Hi[2];
    float gh = 0.f, gl = 0.f, gi = 0.f;
#pragma unroll
    for (int t = 0; t < 2; t++) {
        int d = lane + t * 32;
        float hp = hrow[d], lp = hrow[64 + d], hi = hrow[128 + d];
        float ah = arow[d], al = arow[64 + d];
        Hhp[t] = fmaxf(hp - (ah + inv * hp), 0.f);
        Hlp[t] = fmaxf(al + inv * lp, 0.f);
        Hi [t] = fmaxf(hi, 0.f);
        gh += Hhp[t] * wgh[d];
        gl += Hlp[t] * wgl[d];
        gi += Hi [t] * wgi[d];
    }
#pragma unroll
    for (int o = 16; o > 0; o >>= 1) {
        gh += __shfl_xor_sync(0xFFFFFFFFu, gh, o);
        gl += __shfl_xor_sync(0xFFFFFFFFu, gl, o);
        gi += __shfl_xor_sync(0xFFFFFFFFu, gi, o);
    }
    gh += bgh[0]; gl += bgl[0]; gi += bgi[0];

    float o0 = gh * Hhp[0] + gl * Hlp[0] + gi * Hi[0];
    float o1 = gh * Hhp[1] + gl * Hlp[1] + gi * Hi[1];

    float m = fmaxf(o0, o1);
#pragma unroll
    for (int o = 16; o > 0; o >>= 1) m = fmaxf(m, __shfl_xor_sync(0xFFFFFFFFu, m, o));
    float s = expf(o0 - m) + expf(o1 - m);
#pragma unroll
    for (int o = 16; o > 0; o >>= 1) s += __shfl_xor_sync(0xFFFFFFFFu, s, o);
    float lse = m + logf(s);

    out[(size_t)node * 64 + lane]      = o0 - lse;
    out[(size_t)node * 64 + lane + 32] = o1 - lse;
}

// ---------------- host launch ------------------------------------------------
extern "C" void kernel_launch(void* const* d_in, const int* in_sizes, int n_in,
                              void* d_out, int out_size) {
    const float* x  = (const float*)d_in[0];
    const void*  ei = d_in[1];
    const float* Whp = (const float*)d_in[2];
    const float* bhp = (const float*)d_in[3];
    const float* Wlp = (const float*)d_in[4];
    const float* blp = (const float*)d_in[5];
    const float* Wi  = (const float*)d_in[6];
    const float* bi  = (const float*)d_in[7];
    const float* wgh = (const float*)d_in[8];
    const float* bgh = (const float*)d_in[9];
    const float* wgl = (const float*)d_in[10];
    const float* bgl = (const float*)d_in[11];
    const float* wgi = (const float*)d_in[12];
    const float* bgi = (const float*)d_in[13];
    float* out = (float*)d_out;

    int n = in_sizes[0] / IN_DIM;   // 100000
    int E = in_sizes[1] / 2;        // 3200000
    int nb = (n + 1023) / 1024;

    static cudaStream_t s1 = nullptr;
    static cudaEvent_t ev_root = nullptr, ev_isq = nullptr, ev_side = nullptr;
    if (!s1) {   // first call = uncaptured correctness call: safe to create
        cudaFuncSetAttribute(k_gemm, cudaFuncAttributeMaxDynamicSharedMemorySize, GEMM_SMEM);
        cudaStreamCreateWithFlags(&s1, cudaStreamNonBlocking);
        cudaEventCreateWithFlags(&ev_root, cudaEventDisableTiming);
        cudaEventCreateWithFlags(&ev_isq,  cudaEventDisableTiming);
        cudaEventCreateWithFlags(&ev_side, cudaEventDisableTiming);
    }

    cudaEventRecord(ev_root, 0);
    cudaStreamWaitEvent(s1, ev_root, 0);

    // stream 0 critical path: xh -> prep_w -> gemm (gemm stays at profiled slot idx 3)
    k_detect<<<1, 32, 0, s1>>>(ei, E, n);
    k_xh<<<(n * IN_DIM / 4 + 255) / 256, 256>>>(x, n * IN_DIM / 4);
    k_prep_w<<<(IN_DIM * HCOLS + 255) / 256, 256>>>(Whp, bhp, Wlp, blp, Wi, bi);
    k_gemm<<<(n + 127) / 128, 512, GEMM_SMEM>>>(n);
    // side stream: CSR prep
    k_zero<<<(n + 255) / 256, 256, 0, s1>>>(n);
    k_deg<<<(E + 255) / 256, 256, 0, s1>>>(ei, E, n);
    k_scan1<<<nb, 1024, 0, s1>>>(n);
    k_scan2<<<1, 128, 0, s1>>>(nb);
    k_scan3<<<(n + 255) / 256, 256, 0, s1>>>(n);
    cudaEventRecord(ev_isq, s1);                          // isq/inv ready
    k_scatter<<<(E + 255) / 256, 256, 0, s1>>>(ei, E, n);
    cudaEventRecord(ev_side, s1);                         // CSR ready

    cudaStreamWaitEvent(0, ev_isq, 0);
    k_prescale<<<(n * 32 + 255) / 256, 256>>>(n);

    cudaStreamWaitEvent(0, ev_side, 0);
    k_final<<<(n + 7) / 8, 256>>>(wgh, bgh, wgl, bgl, wgi, bgi, out, n);
}